// round 1
// baseline (speedup 1.0000x reference)
#include <cuda_runtime.h>
#include <cuda_bf16.h>
#include <math.h>

// Problem constants
#define B_   2
#define T_   1024
#define C_   2048
#define NCH  8
#define KLAT 32
#define NKV  4
#define NREP 4
#define D_   128

// Scratch (device globals; no allocation allowed)
__device__ float g_q[B_ * T_ * C_];          // (B,T, nkv*nrep*D) = 16 MB
__device__ float g_k[B_ * NCH * KLAT * NKV * D_]; // (B,N,K, nkv*D) = 1 MB
__device__ float g_v[B_ * NCH * KLAT * NKV * D_]; // 1 MB
__device__ float g_y[B_ * T_ * C_];          // 16 MB

// ---------------------------------------------------------------------------
// Tiled fp32 SGEMM: C[M,N] = A[M,K] * B[K,N]  (all row-major),
// optional epilogue scale = tanh(*scale_ptr).
// BM=BN=128, BK=16, 256 threads, 8x8 per-thread microtile.
// All dims used here are multiples of the tile sizes -> no bounds checks.
// ---------------------------------------------------------------------------
#define BM 128
#define BN 128
#define BK 16
#define TM 8
#define TN 8

__global__ void __launch_bounds__(256, 2) sgemm_kernel(
    const float* __restrict__ A, const float* __restrict__ Bm, float* __restrict__ C,
    int M, int N, int K, const float* __restrict__ scale_ptr)
{
    __shared__ float As[BK][BM + 4];  // padded to dodge store conflicts
    __shared__ float Bs[BK][BN];

    const int tid = threadIdx.x;
    const int bx = blockIdx.x;   // N tile
    const int by = blockIdx.y;   // M tile

    const float* Ab = A + (size_t)by * BM * K;
    const float* Bb = Bm + (size_t)bx * BN;
    float* Cb = C + (size_t)by * BM * N + (size_t)bx * BN;

    // A tile loader: 128 rows x 16 cols = 512 float4 (4 per row), 2 per thread
    const int a_row  = tid >> 2;        // 0..63 (and +64)
    const int a_col4 = (tid & 3) * 4;   // 0,4,8,12
    // B tile loader: 16 rows x 128 cols = 512 float4 (32 per row), 2 per thread
    const int b_row  = tid >> 5;        // 0..7 (and +8)
    const int b_col4 = (tid & 31) * 4;

    const int ty = tid >> 4;  // 0..15 -> M
    const int tx = tid & 15;  // 0..15 -> N

    float acc[TM][TN];
    #pragma unroll
    for (int i = 0; i < TM; i++)
        #pragma unroll
        for (int j = 0; j < TN; j++) acc[i][j] = 0.0f;

    for (int k0 = 0; k0 < K; k0 += BK) {
        #pragma unroll
        for (int i = 0; i < 2; i++) {
            int r = a_row + i * 64;
            float4 v = *(const float4*)(Ab + (size_t)r * K + k0 + a_col4);
            As[a_col4 + 0][r] = v.x;
            As[a_col4 + 1][r] = v.y;
            As[a_col4 + 2][r] = v.z;
            As[a_col4 + 3][r] = v.w;
        }
        #pragma unroll
        for (int i = 0; i < 2; i++) {
            int r = b_row + i * 8;
            *(float4*)&Bs[r][b_col4] =
                *(const float4*)(Bb + (size_t)(k0 + r) * N + b_col4);
        }
        __syncthreads();

        #pragma unroll
        for (int kk = 0; kk < BK; kk++) {
            float ar[TM], br[TN];
            #pragma unroll
            for (int i = 0; i < TM; i++) ar[i] = As[kk][ty * TM + i];
            #pragma unroll
            for (int j = 0; j < TN; j++) br[j] = Bs[kk][tx * TN + j];
            #pragma unroll
            for (int i = 0; i < TM; i++)
                #pragma unroll
                for (int j = 0; j < TN; j++)
                    acc[i][j] = fmaf(ar[i], br[j], acc[i][j]);
        }
        __syncthreads();
    }

    float scale = 1.0f;
    if (scale_ptr) scale = tanhf(*scale_ptr);

    #pragma unroll
    for (int i = 0; i < TM; i++) {
        float* crow = Cb + (size_t)(ty * TM + i) * N + tx * TN;
        #pragma unroll
        for (int j = 0; j < TN; j += 4) {
            float4 v;
            v.x = acc[i][j + 0] * scale;
            v.y = acc[i][j + 1] * scale;
            v.z = acc[i][j + 2] * scale;
            v.w = acc[i][j + 3] * scale;
            *(float4*)(crow + j) = v;
        }
    }
}

// ---------------------------------------------------------------------------
// Tiny-K attention. One block per token (B*T = 2048 blocks), 128 threads.
// warp = kv group g (4 groups). Phase 1: lane = key (32 keys), dot over D=128
// against 4 rep-head q vectors staged in smem. Phase 2: softmax across warp.
// Phase 3: lane = d-chunk (4 floats), accumulate over 32 keys (coalesced V).
// K/V total is 2 MB -> all loads are L2 hits.
// ---------------------------------------------------------------------------
__global__ void __launch_bounds__(128) attn_kernel(
    const float* __restrict__ q, const float* __restrict__ k,
    const float* __restrict__ v, const int* __restrict__ mask,
    float* __restrict__ y)
{
    const int bt   = blockIdx.x;        // 0..B*T-1
    const int b    = bt >> 10;          // T = 1024
    const int g    = threadIdx.x >> 5;  // kv group
    const int lane = threadIdx.x & 31;

    const int n = mask[bt];             // channel in [0, NCH)

    const size_t kv_chan = ((size_t)(b * NCH + n)) * KLAT * (NKV * D_);
    const float* kbase = k + kv_chan + g * D_;
    const float* vbase = v + kv_chan + g * D_;
    const float* qbase = q + (size_t)bt * C_ + g * (NREP * D_);

    __shared__ float qs[4][NREP * D_];  // [g][r*128+d] = 8 KB
    __shared__ float ws[4][NREP][KLAT]; // softmax weights = 2 KB

    // Stage this group's 4 q vectors (512 floats) into smem: 4 float4/lane
    {
        float4* dst = (float4*)&qs[g][0];
        const float4* src = (const float4*)qbase;
        #pragma unroll
        for (int i = 0; i < 4; i++) dst[i * 32 + lane] = src[i * 32 + lane];
    }
    __syncwarp();

    // Phase 1: lane owns key = lane; scores for 4 rep heads
    float s[NREP] = {0.f, 0.f, 0.f, 0.f};
    {
        const float* krow = kbase + (size_t)lane * (NKV * D_);
        #pragma unroll
        for (int i = 0; i < D_ / 4; i++) {
            float4 kk = *(const float4*)(krow + i * 4);
            #pragma unroll
            for (int r = 0; r < NREP; r++) {
                const float* qr = &qs[g][r * D_ + i * 4];
                s[r] = fmaf(kk.x, qr[0], s[r]);
                s[r] = fmaf(kk.y, qr[1], s[r]);
                s[r] = fmaf(kk.z, qr[2], s[r]);
                s[r] = fmaf(kk.w, qr[3], s[r]);
            }
        }
    }
    const float scale = 0.08838834764831845f;  // 1/sqrt(128)

    // Phase 2: softmax over 32 keys (full warp)
    #pragma unroll
    for (int r = 0; r < NREP; r++) {
        float sc = s[r] * scale;
        float m = sc;
        #pragma unroll
        for (int o = 16; o > 0; o >>= 1)
            m = fmaxf(m, __shfl_xor_sync(0xFFFFFFFFu, m, o));
        float e = expf(sc - m);
        float sum = e;
        #pragma unroll
        for (int o = 16; o > 0; o >>= 1)
            sum += __shfl_xor_sync(0xFFFFFFFFu, sum, o);
        ws[g][r][lane] = e / sum;
    }
    __syncwarp();

    // Phase 3: lane owns d-chunk [lane*4, lane*4+4); accumulate over keys
    float4 acc[NREP];
    #pragma unroll
    for (int r = 0; r < NREP; r++) acc[r] = make_float4(0.f, 0.f, 0.f, 0.f);

    #pragma unroll 8
    for (int key = 0; key < KLAT; key++) {
        float4 vv = *(const float4*)(vbase + (size_t)key * (NKV * D_) + lane * 4);
        #pragma unroll
        for (int r = 0; r < NREP; r++) {
            float w = ws[g][r][key];
            acc[r].x = fmaf(w, vv.x, acc[r].x);
            acc[r].y = fmaf(w, vv.y, acc[r].y);
            acc[r].z = fmaf(w, vv.z, acc[r].z);
            acc[r].w = fmaf(w, vv.w, acc[r].w);
        }
    }

    float* ybase = y + (size_t)bt * C_ + g * (NREP * D_);
    #pragma unroll
    for (int r = 0; r < NREP; r++)
        *(float4*)(ybase + r * D_ + lane * 4) = acc[r];
}

// ---------------------------------------------------------------------------
// Launch. Inputs (metadata order):
//   0: x              (B,T,C)       float32
//   1: channel_states (B,N,K,C)     float32
//   2: channel_mask   (B,T)         int32
//   3: Wq             (C, 16*128)   float32
//   4: Wk             (C, 4*128)    float32
//   5: Wv             (C, 4*128)    float32
//   6: Wo             (16*128, C)   float32
//   7: gate           (1,)          float32
// output: (B,T,C) float32
// ---------------------------------------------------------------------------
extern "C" void kernel_launch(void* const* d_in, const int* in_sizes, int n_in,
                              void* d_out, int out_size)
{
    const float* x    = (const float*)d_in[0];
    const float* cs   = (const float*)d_in[1];
    const int*   mask = (const int*)d_in[2];
    const float* Wq   = (const float*)d_in[3];
    const float* Wk   = (const float*)d_in[4];
    const float* Wv   = (const float*)d_in[5];
    const float* Wo   = (const float*)d_in[6];
    const float* gate = (const float*)d_in[7];
    float* out = (float*)d_out;

    float* q = nullptr; float* kk = nullptr; float* vv = nullptr; float* y = nullptr;
    cudaGetSymbolAddress((void**)&q,  g_q);
    cudaGetSymbolAddress((void**)&kk, g_k);
    cudaGetSymbolAddress((void**)&vv, g_v);
    cudaGetSymbolAddress((void**)&y,  g_y);

    const int M1 = B_ * T_;          // 2048
    const int Mkv = B_ * NCH * KLAT; // 512
    const int Nkv = NKV * D_;        // 512

    // Q projection: (2048 x 2048) x (2048 x 2048)
    {
        dim3 grid(C_ / BN, M1 / BM);
        sgemm_kernel<<<grid, 256>>>(x, Wq, q, M1, C_, C_, nullptr);
    }
    // K/V projections: (512 x 2048) x (2048 x 512)
    {
        dim3 grid(Nkv / BN, Mkv / BM);
        sgemm_kernel<<<grid, 256>>>(cs, Wk, kk, Mkv, Nkv, C_, nullptr);
        sgemm_kernel<<<grid, 256>>>(cs, Wv, vv, Mkv, Nkv, C_, nullptr);
    }
    // Attention
    attn_kernel<<<B_ * T_, 128>>>(q, kk, vv, mask, y);
    // Output projection + tanh(gate): (2048 x 2048) x (2048 x 2048)
    {
        dim3 grid(C_ / BN, M1 / BM);
        sgemm_kernel<<<grid, 256>>>(y, Wo, out, M1, C_, C_, gate);
    }
}

// round 5
// speedup vs baseline: 3.4360x; 3.4360x over previous
#include <cuda_runtime.h>
#include <math.h>
#include <cstdint>

// ---------------------------------------------------------------------------
// Problem constants
// ---------------------------------------------------------------------------
#define B_   2
#define T_   1024
#define C_   2048
#define NCH  8
#define KLAT 32
#define NKV  4
#define NREP 4
#define D_   128

#define KV_SPLIT 8

// Scratch (device globals; allocation is forbidden)
__device__ float g_q[B_ * T_ * C_];                 // 16 MB
__device__ float g_y[B_ * T_ * C_];                 // 16 MB (tf32-rounded by attn)
__device__ float g_k[B_ * NCH * KLAT * NKV * D_];   // 1 MB
__device__ float g_v[B_ * NCH * KLAT * NKV * D_];   // 1 MB
__device__ float g_part[KV_SPLIT * 512 * 512];      // 8 MB split-K partials
// tf32-pre-rounded inputs (unbiased rna rounding; mma then computes exactly)
__device__ float g_xt [B_ * T_ * C_];               // 16 MB
__device__ float g_cst[B_ * NCH * KLAT * C_];       // 4 MB
__device__ float g_Wqt[C_ * C_];                    // 16 MB
__device__ float g_Wkt[C_ * NKV * D_];              // 4 MB
__device__ float g_Wvt[C_ * NKV * D_];              // 4 MB
__device__ float g_Wot[C_ * C_];                    // 16 MB

// ---------------------------------------------------------------------------
// Helpers
// ---------------------------------------------------------------------------
__device__ __forceinline__ uint32_t smem_u32(const void* p) {
    uint32_t a;
    asm("{ .reg .u64 t; cvta.to.shared.u64 t, %1; cvt.u32.u64 %0, t; }"
        : "=r"(a) : "l"(p));
    return a;
}

__device__ __forceinline__ uint32_t f32_to_tf32(float f) {
    uint32_t r;
    asm("cvt.rna.tf32.f32 %0, %1;" : "=r"(r) : "f"(f));
    return r;
}

// ---------------------------------------------------------------------------
// Elementwise tf32 pre-rounding (rna, unbiased). n divisible by 1024.
// ---------------------------------------------------------------------------
__global__ void __launch_bounds__(256) cvt_tf32_kernel(
    const float* __restrict__ in, float* __restrict__ out, int n)
{
    int i = (blockIdx.x * 256 + threadIdx.x) * 4;
    if (i < n) {
        float4 v = *(const float4*)(in + i);
        uint4 t;
        t.x = f32_to_tf32(v.x); t.y = f32_to_tf32(v.y);
        t.z = f32_to_tf32(v.z); t.w = f32_to_tf32(v.w);
        *(uint4*)(out + i) = t;
    }
}

// ---------------------------------------------------------------------------
// tf32 mma.sync GEMM: C[M,N] = A[M,K] @ Bw[K,N], both row-major, fp32 in/out.
// Block tile 128x256, 8 warps (2 m x 4 n), warp tile 64x64, BK=32 floats.
// 3-stage cp.async pipeline into fragment-native XOR-swizzled SMEM.
//  A[row][k] (row 0..127, k 0..31 within chunk):
//    t=row>>4, rowin=row&15, rowbit=rowin>>3, row8=rowin&7
//    s=k>>3, cbit=(k>>2)&1, r=rowbit+2*cbit
//    phys_f = (t*4+s)*128 + r*32 + ((row8*4 + (k&3)) ^ (4*((2*s)^cbit)))
//  B[k][n] (k 0..31, n 0..255):
//    nt=n>>3, n8=n&7, s=k>>3, r=(k>>2)&1
//    phys_f = A_FLOATS + (nt*4+s)*64 + r*32 + (((k&3)*8 + n8) ^ (8*(nt&3)))
// Each thread's gmem float4 is one contiguous 16B cp.async; fragment loads
// are conflict-free LDS.32 (verified vs PTX m16n8k8 tf32 fragment layout).
// Split-K via blockIdx.z: k range [z*k_len, (z+1)*k_len), out += z*M*N.
// ---------------------------------------------------------------------------
#define BM 128
#define BN 256
#define BKF 32
#define STAGES 3
#define A_BYTES (BM * BKF * 4)                 // 16384
#define B_BYTES (BN * BKF * 4)                 // 32768
#define STAGE_BYTES (A_BYTES + B_BYTES)        // 49152
#define GEMM_SMEM (STAGES * STAGE_BYTES)       // 147456

__global__ void __launch_bounds__(256, 1) mma_gemm_kernel(
    const float* __restrict__ A, const float* __restrict__ Bw,
    float* __restrict__ Cout, int M, int N, int K, int k_len,
    const float* __restrict__ scale_ptr)
{
    extern __shared__ char smem[];
    const uint32_t s_base = smem_u32(smem);

    const int tid    = threadIdx.x;
    const int lane   = tid & 31;
    const int wid    = tid >> 5;
    const int warp_m = wid & 1;   // 2 warps in m
    const int warp_n = wid >> 1;  // 4 warps in n

    const int m0  = blockIdx.y * BM;
    const int n0  = blockIdx.x * BN;
    const int z   = blockIdx.z;
    const int kc0 = z * (k_len / BKF);  // first chunk index
    const int nch = k_len / BKF;
    float* outp = Cout + (size_t)z * M * N;

    // ---- per-thread loader precompute (smem offsets invariant per chunk) ----
    // A tile: 128 rows x 8 float4/row = 1024 float4; 4 per thread
    uint32_t sa_off[4], ga_off[4];
    #pragma unroll
    for (int j = 0; j < 4; j++) {
        int f = tid + j * 256;
        int row = f >> 3, c4 = f & 7;           // c4: float4 index in row (k)
        int t = row >> 4, rowin = row & 15;
        int rowbit = rowin >> 3, row8 = rowin & 7;
        int s = c4 >> 1, cbit = c4 & 1;
        int r = rowbit + 2 * cbit;
        int l0 = (row8 * 4) ^ (4 * ((2 * s) ^ cbit));
        sa_off[j] = (uint32_t)(((t * 4 + s) * 128 + r * 32 + l0) * 4);
        ga_off[j] = (uint32_t)((m0 + row) * K + c4 * 4);
    }
    // B tile: 32 k-rows x 64 float4/row = 2048 float4; 8 per thread
    uint32_t sb_off[8], gb_off[8];
    #pragma unroll
    for (int j = 0; j < 8; j++) {
        int f = tid + j * 256;
        int k = f >> 6, n4 = f & 63;            // FIXED: 64 float4 per k-row
        int nt = n4 >> 1, nb = n4 & 1;          // nt in 0..31 (8-col n tile)
        int s = k >> 3, r = (k >> 2) & 1;
        int lp0 = (((k & 3) * 8) + nb * 4) ^ (8 * (nt & 3));
        sb_off[j] = (uint32_t)(A_BYTES + ((nt * 4 + s) * 64 + r * 32 + lp0) * 4);
        gb_off[j] = (uint32_t)(k * N + n0 + n4 * 4);
    }

    auto issue = [&](int chunk, int buf) {
        uint32_t sb = s_base + buf * STAGE_BYTES;
        const float* ga = A  + (size_t)(kc0 + chunk) * BKF;
        const float* gb = Bw + (size_t)(kc0 + chunk) * BKF * N;
        #pragma unroll
        for (int j = 0; j < 4; j++)
            asm volatile("cp.async.cg.shared.global [%0], [%1], 16;"
                :: "r"(sb + sa_off[j]), "l"(ga + ga_off[j]));
        #pragma unroll
        for (int j = 0; j < 8; j++)
            asm volatile("cp.async.cg.shared.global [%0], [%1], 16;"
                :: "r"(sb + sb_off[j]), "l"(gb + gb_off[j]));
        asm volatile("cp.async.commit_group;" ::: "memory");
    };

    float acc[4][8][4];
    #pragma unroll
    for (int a = 0; a < 4; a++)
        #pragma unroll
        for (int b = 0; b < 8; b++)
            #pragma unroll
            for (int c = 0; c < 4; c++) acc[a][b][c] = 0.0f;

    const int npro = (STAGES - 1 < nch) ? (STAGES - 1) : nch;
    for (int p = 0; p < npro; p++) issue(p, p % STAGES);

    for (int i = 0; i < nch; i++) {
        asm volatile("cp.async.wait_group %0;" :: "n"(STAGES - 2) : "memory");
        __syncthreads();

        const uint32_t ab = s_base + (i % STAGES) * STAGE_BYTES;
        const uint32_t bb = ab + A_BYTES;

        #pragma unroll
        for (int s = 0; s < 4; s++) {
            uint32_t areg[4][4];
            #pragma unroll
            for (int mt = 0; mt < 4; mt++) {
                int t = warp_m * 4 + mt;
                uint32_t base = ab + ((t * 4 + s) * 128) * 4;
                #pragma unroll
                for (int r = 0; r < 4; r++) {
                    uint32_t addr = base +
                        (r * 32 + (lane ^ (4 * ((2 * s) ^ (r >> 1))))) * 4;
                    asm volatile("ld.shared.b32 %0, [%1];"
                        : "=r"(areg[mt][r]) : "r"(addr));
                }
            }
            uint32_t breg[8][2];
            #pragma unroll
            for (int nt8 = 0; nt8 < 8; nt8++) {
                int nt = warp_n * 8 + nt8;
                uint32_t base = bb + ((nt * 4 + s) * 64) * 4;
                uint32_t lp = (uint32_t)((((lane & 3) * 8) + (lane >> 2))
                                         ^ (8 * (nt & 3)));
                #pragma unroll
                for (int r = 0; r < 2; r++) {
                    uint32_t addr = base + (r * 32 + lp) * 4;
                    asm volatile("ld.shared.b32 %0, [%1];"
                        : "=r"(breg[nt8][r]) : "r"(addr));
                }
            }
            #pragma unroll
            for (int mt = 0; mt < 4; mt++)
                #pragma unroll
                for (int nt8 = 0; nt8 < 8; nt8++)
                    asm volatile(
                        "mma.sync.aligned.m16n8k8.row.col.f32.tf32.tf32.f32 "
                        "{%0,%1,%2,%3}, {%4,%5,%6,%7}, {%8,%9}, {%0,%1,%2,%3};"
                        : "+f"(acc[mt][nt8][0]), "+f"(acc[mt][nt8][1]),
                          "+f"(acc[mt][nt8][2]), "+f"(acc[mt][nt8][3])
                        : "r"(areg[mt][0]), "r"(areg[mt][1]),
                          "r"(areg[mt][2]), "r"(areg[mt][3]),
                          "r"(breg[nt8][0]), "r"(breg[nt8][1]));
        }

        if (i + STAGES - 1 < nch)
            issue(i + STAGES - 1, (i + STAGES - 1) % STAGES);
    }

    // Epilogue
    float scale = 1.0f;
    if (scale_ptr) scale = tanhf(*scale_ptr);
    const int g = lane >> 2, tig = lane & 3;
    #pragma unroll
    for (int mt = 0; mt < 4; mt++) {
        int row = m0 + warp_m * 64 + mt * 16 + g;
        #pragma unroll
        for (int nt8 = 0; nt8 < 8; nt8++) {
            int col = n0 + warp_n * 64 + nt8 * 8 + 2 * tig;
            float2 v0, v1;
            v0.x = acc[mt][nt8][0] * scale; v0.y = acc[mt][nt8][1] * scale;
            v1.x = acc[mt][nt8][2] * scale; v1.y = acc[mt][nt8][3] * scale;
            *(float2*)(outp + (size_t)row * N + col) = v0;
            *(float2*)(outp + (size_t)(row + 8) * N + col) = v1;
        }
    }
}

// ---------------------------------------------------------------------------
// Deterministic split-K reduction: out[i] = sum_z part[z][i]
// ---------------------------------------------------------------------------
__global__ void __launch_bounds__(256) reduce_split_kernel(
    const float* __restrict__ part, float* __restrict__ out, int n)
{
    int i = (blockIdx.x * 256 + threadIdx.x) * 4;
    if (i < n) {
        float4 s = *(const float4*)(part + i);
        #pragma unroll
        for (int zz = 1; zz < KV_SPLIT; zz++) {
            float4 p = *(const float4*)(part + (size_t)zz * n + i);
            s.x += p.x; s.y += p.y; s.z += p.z; s.w += p.w;
        }
        *(float4*)(out + i) = s;
    }
}

// ---------------------------------------------------------------------------
// Tiny-K attention (known-good). One block per token, 128 threads.
// Output y is written tf32-rounded (rna) so the O-projection mma is exact.
// ---------------------------------------------------------------------------
__global__ void __launch_bounds__(128) attn_kernel(
    const float* __restrict__ q, const float* __restrict__ k,
    const float* __restrict__ v, const int* __restrict__ mask,
    float* __restrict__ y)
{
    const int bt   = blockIdx.x;
    const int b    = bt >> 10;
    const int g    = threadIdx.x >> 5;
    const int lane = threadIdx.x & 31;

    const int n = mask[bt];

    const size_t kv_chan = ((size_t)(b * NCH + n)) * KLAT * (NKV * D_);
    const float* kbase = k + kv_chan + g * D_;
    const float* vbase = v + kv_chan + g * D_;
    const float* qbase = q + (size_t)bt * C_ + g * (NREP * D_);

    __shared__ float qs[4][NREP * D_];
    __shared__ float ws[4][NREP][KLAT];

    {
        float4* dst = (float4*)&qs[g][0];
        const float4* src = (const float4*)qbase;
        #pragma unroll
        for (int i = 0; i < 4; i++) dst[i * 32 + lane] = src[i * 32 + lane];
    }
    __syncwarp();

    float s[NREP] = {0.f, 0.f, 0.f, 0.f};
    {
        const float* krow = kbase + (size_t)lane * (NKV * D_);
        #pragma unroll
        for (int i = 0; i < D_ / 4; i++) {
            float4 kk = *(const float4*)(krow + i * 4);
            #pragma unroll
            for (int r = 0; r < NREP; r++) {
                const float* qr = &qs[g][r * D_ + i * 4];
                s[r] = fmaf(kk.x, qr[0], s[r]);
                s[r] = fmaf(kk.y, qr[1], s[r]);
                s[r] = fmaf(kk.z, qr[2], s[r]);
                s[r] = fmaf(kk.w, qr[3], s[r]);
            }
        }
    }
    const float scale = 0.08838834764831845f;

    #pragma unroll
    for (int r = 0; r < NREP; r++) {
        float sc = s[r] * scale;
        float m = sc;
        #pragma unroll
        for (int o = 16; o > 0; o >>= 1)
            m = fmaxf(m, __shfl_xor_sync(0xFFFFFFFFu, m, o));
        float e = expf(sc - m);
        float sum = e;
        #pragma unroll
        for (int o = 16; o > 0; o >>= 1)
            sum += __shfl_xor_sync(0xFFFFFFFFu, sum, o);
        ws[g][r][lane] = e / sum;
    }
    __syncwarp();

    float4 acc[NREP];
    #pragma unroll
    for (int r = 0; r < NREP; r++) acc[r] = make_float4(0.f, 0.f, 0.f, 0.f);

    #pragma unroll 8
    for (int key = 0; key < KLAT; key++) {
        float4 vv = *(const float4*)(vbase + (size_t)key * (NKV * D_) + lane * 4);
        #pragma unroll
        for (int r = 0; r < NREP; r++) {
            float w = ws[g][r][key];
            acc[r].x = fmaf(w, vv.x, acc[r].x);
            acc[r].y = fmaf(w, vv.y, acc[r].y);
            acc[r].z = fmaf(w, vv.z, acc[r].z);
            acc[r].w = fmaf(w, vv.w, acc[r].w);
        }
    }

    float* ybase = y + (size_t)bt * C_ + g * (NREP * D_);
    #pragma unroll
    for (int r = 0; r < NREP; r++) {
        uint4 t;
        t.x = f32_to_tf32(acc[r].x); t.y = f32_to_tf32(acc[r].y);
        t.z = f32_to_tf32(acc[r].z); t.w = f32_to_tf32(acc[r].w);
        *(uint4*)(ybase + r * D_ + lane * 4) = t;
    }
}

// ---------------------------------------------------------------------------
// Launch. Inputs: x, channel_states, channel_mask, Wq, Wk, Wv, Wo, gate.
// ---------------------------------------------------------------------------
extern "C" void kernel_launch(void* const* d_in, const int* in_sizes, int n_in,
                              void* d_out, int out_size)
{
    const float* x    = (const float*)d_in[0];
    const float* cs   = (const float*)d_in[1];
    const int*   mask = (const int*)d_in[2];
    const float* Wq   = (const float*)d_in[3];
    const float* Wk   = (const float*)d_in[4];
    const float* Wv   = (const float*)d_in[5];
    const float* Wo   = (const float*)d_in[6];
    const float* gate = (const float*)d_in[7];
    float* out = (float*)d_out;

    float *q, *y, *kk, *vv, *part, *xt, *cst, *Wqt, *Wkt, *Wvt, *Wot;
    cudaGetSymbolAddress((void**)&q,    g_q);
    cudaGetSymbolAddress((void**)&y,    g_y);
    cudaGetSymbolAddress((void**)&kk,   g_k);
    cudaGetSymbolAddress((void**)&vv,   g_v);
    cudaGetSymbolAddress((void**)&part, g_part);
    cudaGetSymbolAddress((void**)&xt,   g_xt);
    cudaGetSymbolAddress((void**)&cst,  g_cst);
    cudaGetSymbolAddress((void**)&Wqt,  g_Wqt);
    cudaGetSymbolAddress((void**)&Wkt,  g_Wkt);
    cudaGetSymbolAddress((void**)&Wvt,  g_Wvt);
    cudaGetSymbolAddress((void**)&Wot,  g_Wot);

    cudaFuncSetAttribute(mma_gemm_kernel,
                         cudaFuncAttributeMaxDynamicSharedMemorySize, GEMM_SMEM);

    const int M1  = B_ * T_;          // 2048
    const int Mkv = B_ * NCH * KLAT;  // 512
    const int Nkv = NKV * D_;         // 512

    // tf32 pre-rounding (rna) of all mma inputs
    cvt_tf32_kernel<<<(M1 * C_) / 1024, 256>>>(x,  xt,  M1 * C_);
    cvt_tf32_kernel<<<(Mkv * C_) / 1024, 256>>>(cs, cst, Mkv * C_);
    cvt_tf32_kernel<<<(C_ * C_) / 1024, 256>>>(Wq, Wqt, C_ * C_);
    cvt_tf32_kernel<<<(C_ * Nkv) / 1024, 256>>>(Wk, Wkt, C_ * Nkv);
    cvt_tf32_kernel<<<(C_ * Nkv) / 1024, 256>>>(Wv, Wvt, C_ * Nkv);
    cvt_tf32_kernel<<<(C_ * C_) / 1024, 256>>>(Wo, Wot, C_ * C_);

    // Q projection: (2048x2048) @ (2048x2048)
    mma_gemm_kernel<<<dim3(C_ / BN, M1 / BM, 1), 256, GEMM_SMEM>>>(
        xt, Wqt, q, M1, C_, C_, C_, nullptr);

    // K/V projections: (512x2048) @ (2048x512), split-K=8 + reduction
    mma_gemm_kernel<<<dim3(Nkv / BN, Mkv / BM, KV_SPLIT), 256, GEMM_SMEM>>>(
        cst, Wkt, part, Mkv, Nkv, C_, C_ / KV_SPLIT, nullptr);
    reduce_split_kernel<<<(Mkv * Nkv) / 1024, 256>>>(part, kk, Mkv * Nkv);
    mma_gemm_kernel<<<dim3(Nkv / BN, Mkv / BM, KV_SPLIT), 256, GEMM_SMEM>>>(
        cst, Wvt, part, Mkv, Nkv, C_, C_ / KV_SPLIT, nullptr);
    reduce_split_kernel<<<(Mkv * Nkv) / 1024, 256>>>(part, vv, Mkv * Nkv);

    // Attention (writes y tf32-rounded)
    attn_kernel<<<B_ * T_, 128>>>(q, kk, vv, mask, y);

    // Output projection + tanh(gate)
    mma_gemm_kernel<<<dim3(C_ / BN, M1 / BM, 1), 256, GEMM_SMEM>>>(
        y, Wot, out, M1, C_, C_, C_, gate);
}

// round 8
// speedup vs baseline: 4.7051x; 1.3693x over previous
#include <cuda_runtime.h>
#include <math.h>
#include <cstdint>

// ---------------------------------------------------------------------------
// Problem constants
// ---------------------------------------------------------------------------
#define B_   2
#define T_   1024
#define C_   2048
#define NCH  8
#define KLAT 32
#define NKV  4
#define NREP 4
#define D_   128

#define KV_SPLIT 8

// Scratch (device globals; allocation is forbidden)
__device__ float g_q[B_ * T_ * C_];                 // 16 MB
__device__ float g_y[B_ * T_ * C_];                 // 16 MB
__device__ float g_k[B_ * NCH * KLAT * NKV * D_];   // 1 MB
__device__ float g_v[B_ * NCH * KLAT * NKV * D_];   // 1 MB
__device__ float g_part[KV_SPLIT * 512 * 512];      // 8 MB split-K partials
// Fragment-order, tf32-rounded operands
__device__ float g_xA [B_ * T_ * C_];               // 16 MB
__device__ float g_csA[B_ * NCH * KLAT * C_];       // 4 MB
__device__ float g_yA [B_ * T_ * C_];               // 16 MB
__device__ float g_WqB[C_ * C_];                    // 16 MB
__device__ float g_WkB[C_ * NKV * D_];              // 4 MB
__device__ float g_WvB[C_ * NKV * D_];              // 4 MB
__device__ float g_WoB[C_ * C_];                    // 16 MB

// ---------------------------------------------------------------------------
// Helpers
// ---------------------------------------------------------------------------
__device__ __forceinline__ uint32_t smem_u32(const void* p) {
    uint32_t a;
    asm("{ .reg .u64 t; cvta.to.shared.u64 t, %1; cvt.u32.u64 %0, t; }"
        : "=r"(a) : "l"(p));
    return a;
}

__device__ __forceinline__ float f32_round_tf32(float f) {
    uint32_t r;
    asm("cvt.rna.tf32.f32 %0, %1;" : "=r"(r) : "f"(f));
    return __uint_as_float(r);
}

// ---------------------------------------------------------------------------
// Reformat A (fp32 [M,K] row-major -> fragment order, tf32-rounded).
// Unit u = one 16B output = regs a0..a3 of one (rowblk, chunk, t, s, lane).
//   a0=(g,tig) a1=(g+8,tig) a2=(g,tig+4) a3=(g+8,tig+4), g=lane/4, tig=lane%4
// Layout: floatIdx = ((rb*(K/32)+c)*1024 + (t*4+s)*32 + lane)*4 + reg
// ---------------------------------------------------------------------------
__global__ void __launch_bounds__(256) reformat_A_kernel(
    const float* __restrict__ src, float* __restrict__ dst, int K)
{
    int u = blockIdx.x * 256 + threadIdx.x;      // total units = M*K/4
    int lane = u & 31;
    int ts   = (u >> 5) & 31;                    // t*4+s
    int t    = ts >> 2, s = ts & 3;
    int nch  = K >> 5;
    int cu   = u >> 10;                          // rb*nch + c
    int c    = cu % nch;
    int rb   = cu / nch;
    int g    = lane >> 2, tig = lane & 3;
    int row  = rb * 128 + t * 16 + g;
    int k    = c * 32 + s * 8 + tig;

    const float* p0 = src + (size_t)row * K + k;
    const float* p1 = src + (size_t)(row + 8) * K + k;
    float4 o;
    o.x = f32_round_tf32(p0[0]);
    o.y = f32_round_tf32(p1[0]);
    o.z = f32_round_tf32(p0[4]);
    o.w = f32_round_tf32(p1[4]);
    *(float4*)(dst + (size_t)u * 4) = o;
}

// ---------------------------------------------------------------------------
// Reformat B (fp32 [K,N] row-major -> fragment order, tf32-rounded).
// Unit u = one 8B output = regs b0,b1 of one (nblk, chunk, nt, s, lane).
//   b0=(k=tig, n=g) b1=(k=tig+4, n=g) relative to (c*32+s*8, nb*256+nt*8)
// Layout: floatIdx = ((nb*(K/32)+c)*4096 + (nt*4+s)*32 + lane)*2 + reg
// ---------------------------------------------------------------------------
__global__ void __launch_bounds__(256) reformat_B_kernel(
    const float* __restrict__ src, float* __restrict__ dst, int K, int N)
{
    int u = blockIdx.x * 256 + threadIdx.x;      // total units = K*N/2
    int lane = u & 31;
    int nts  = (u >> 5) & 127;                   // nt*4+s
    int s    = nts & 3, nt = nts >> 2;
    int nch  = K >> 5;
    int cu   = u >> 12;                          // nb*nch + c
    int c    = cu % nch;
    int nb   = cu / nch;
    int g    = lane >> 2, tig = lane & 3;
    int k    = c * 32 + s * 8 + tig;
    int n    = nb * 256 + nt * 8 + g;

    float2 o;
    o.x = f32_round_tf32(src[(size_t)k * N + n]);
    o.y = f32_round_tf32(src[(size_t)(k + 4) * N + n]);
    *(float2*)(dst + (size_t)u * 2) = o;
}

// ---------------------------------------------------------------------------
// tf32 mma.sync GEMM on fragment-order operands.
// Block tile 128x256, 8 warps (2 m x 4 n), warp tile 64x64, BK=32 floats.
// 3-stage cp.async pipeline; chunk blocks are CONTIGUOUS in gmem.
// Fragment loads: LDS.128 (A) / LDS.64 (B), conflict-free.
// Split-K via blockIdx.z.
// ---------------------------------------------------------------------------
#define BM 128
#define BN 256
#define STAGES 3
#define A_BYTES (BM * 32 * 4)                  // 16384 per chunk
#define B_BYTES (BN * 32 * 4)                  // 32768 per chunk
#define STAGE_BYTES (A_BYTES + B_BYTES)        // 49152
#define GEMM_SMEM (STAGES * STAGE_BYTES)       // 147456

__global__ void __launch_bounds__(256, 1) mma_gemm_kernel(
    const float* __restrict__ Afrag, const float* __restrict__ Bfrag,
    float* __restrict__ Cout, int M, int N, int K, int k_len,
    const float* __restrict__ scale_ptr)
{
    extern __shared__ char smem[];
    const uint32_t s_base = smem_u32(smem);

    const int tid    = threadIdx.x;
    const int lane   = tid & 31;
    const int wid    = tid >> 5;
    const int warp_m = wid & 1;
    const int warp_n = wid >> 1;

    const int rb  = blockIdx.y;
    const int nb  = blockIdx.x;
    const int z   = blockIdx.z;
    const int nchK = K >> 5;
    const int kc0 = z * (k_len >> 5);
    const int nch = k_len >> 5;
    float* outp = Cout + (size_t)z * M * N;

    const float* AC = Afrag + (size_t)rb * nchK * 4096;
    const float* BC = Bfrag + (size_t)nb * nchK * 8192;

    auto issue = [&](int chunk, int buf) {
        uint32_t sb = s_base + buf * STAGE_BYTES;
        const float* ga = AC + (size_t)(kc0 + chunk) * 4096;
        const float* gb = BC + (size_t)(kc0 + chunk) * 8192;
        #pragma unroll
        for (int j = 0; j < 4; j++)
            asm volatile("cp.async.cg.shared.global [%0], [%1], 16;"
                :: "r"(sb + (tid + j * 256) * 16), "l"(ga + (tid + j * 256) * 4));
        #pragma unroll
        for (int j = 0; j < 8; j++)
            asm volatile("cp.async.cg.shared.global [%0], [%1], 16;"
                :: "r"(sb + A_BYTES + (tid + j * 256) * 16),
                   "l"(gb + (tid + j * 256) * 4));
        asm volatile("cp.async.commit_group;" ::: "memory");
    };

    float acc[4][8][4];
    #pragma unroll
    for (int a = 0; a < 4; a++)
        #pragma unroll
        for (int b = 0; b < 8; b++)
            #pragma unroll
            for (int c = 0; c < 4; c++) acc[a][b][c] = 0.0f;

    const int npro = (STAGES - 1 < nch) ? (STAGES - 1) : nch;
    for (int p = 0; p < npro; p++) issue(p, p % STAGES);

    for (int i = 0; i < nch; i++) {
        asm volatile("cp.async.wait_group %0;" :: "n"(STAGES - 2) : "memory");
        __syncthreads();

        const uint32_t ab = s_base + (i % STAGES) * STAGE_BYTES;
        const uint32_t bb = ab + A_BYTES;

        #pragma unroll
        for (int s = 0; s < 4; s++) {
            uint32_t areg[4][4];
            #pragma unroll
            for (int mt = 0; mt < 4; mt++) {
                int t = warp_m * 4 + mt;
                uint32_t addr = ab + ((t * 4 + s) * 32 + lane) * 16;
                asm volatile("ld.shared.v4.b32 {%0,%1,%2,%3}, [%4];"
                    : "=r"(areg[mt][0]), "=r"(areg[mt][1]),
                      "=r"(areg[mt][2]), "=r"(areg[mt][3])
                    : "r"(addr));
            }
            uint32_t breg[8][2];
            #pragma unroll
            for (int nt8 = 0; nt8 < 8; nt8++) {
                int nt = warp_n * 8 + nt8;
                uint32_t addr = bb + ((nt * 4 + s) * 32 + lane) * 8;
                asm volatile("ld.shared.v2.b32 {%0,%1}, [%2];"
                    : "=r"(breg[nt8][0]), "=r"(breg[nt8][1])
                    : "r"(addr));
            }
            #pragma unroll
            for (int mt = 0; mt < 4; mt++)
                #pragma unroll
                for (int nt8 = 0; nt8 < 8; nt8++)
                    asm volatile(
                        "mma.sync.aligned.m16n8k8.row.col.f32.tf32.tf32.f32 "
                        "{%0,%1,%2,%3}, {%4,%5,%6,%7}, {%8,%9}, {%0,%1,%2,%3};"
                        : "+f"(acc[mt][nt8][0]), "+f"(acc[mt][nt8][1]),
                          "+f"(acc[mt][nt8][2]), "+f"(acc[mt][nt8][3])
                        : "r"(areg[mt][0]), "r"(areg[mt][1]),
                          "r"(areg[mt][2]), "r"(areg[mt][3]),
                          "r"(breg[nt8][0]), "r"(breg[nt8][1]));
        }

        if (i + STAGES - 1 < nch)
            issue(i + STAGES - 1, (i + STAGES - 1) % STAGES);
    }

    // Epilogue
    float scale = 1.0f;
    if (scale_ptr) scale = tanhf(*scale_ptr);
    const int m0 = rb * BM, n0 = nb * BN;
    const int g = lane >> 2, tig = lane & 3;
    #pragma unroll
    for (int mt = 0; mt < 4; mt++) {
        int row = m0 + warp_m * 64 + mt * 16 + g;
        #pragma unroll
        for (int nt8 = 0; nt8 < 8; nt8++) {
            int col = n0 + warp_n * 64 + nt8 * 8 + 2 * tig;
            float2 v0, v1;
            v0.x = acc[mt][nt8][0] * scale; v0.y = acc[mt][nt8][1] * scale;
            v1.x = acc[mt][nt8][2] * scale; v1.y = acc[mt][nt8][3] * scale;
            *(float2*)(outp + (size_t)row * N + col) = v0;
            *(float2*)(outp + (size_t)(row + 8) * N + col) = v1;
        }
    }
}

// ---------------------------------------------------------------------------
// Deterministic split-K reduction: out[i] = sum_z part[z][i]
// ---------------------------------------------------------------------------
__global__ void __launch_bounds__(256) reduce_split_kernel(
    const float* __restrict__ part, float* __restrict__ out, int n)
{
    int i = (blockIdx.x * 256 + threadIdx.x) * 4;
    if (i < n) {
        float4 s = *(const float4*)(part + i);
        #pragma unroll
        for (int zz = 1; zz < KV_SPLIT; zz++) {
            float4 p = *(const float4*)(part + (size_t)zz * n + i);
            s.x += p.x; s.y += p.y; s.z += p.z; s.w += p.w;
        }
        *(float4*)(out + i) = s;
    }
}

// ---------------------------------------------------------------------------
// Tiny-K attention (known-good). One block per token, 128 threads.
// ---------------------------------------------------------------------------
__global__ void __launch_bounds__(128) attn_kernel(
    const float* __restrict__ q, const float* __restrict__ k,
    const float* __restrict__ v, const int* __restrict__ mask,
    float* __restrict__ y)
{
    const int bt   = blockIdx.x;
    const int b    = bt >> 10;
    const int g    = threadIdx.x >> 5;
    const int lane = threadIdx.x & 31;

    const int n = mask[bt];

    const size_t kv_chan = ((size_t)(b * NCH + n)) * KLAT * (NKV * D_);
    const float* kbase = k + kv_chan + g * D_;
    const float* vbase = v + kv_chan + g * D_;
    const float* qbase = q + (size_t)bt * C_ + g * (NREP * D_);

    __shared__ float qs[4][NREP * D_];
    __shared__ float ws[4][NREP][KLAT];

    {
        float4* dst = (float4*)&qs[g][0];
        const float4* src = (const float4*)qbase;
        #pragma unroll
        for (int i = 0; i < 4; i++) dst[i * 32 + lane] = src[i * 32 + lane];
    }
    __syncwarp();

    float s[NREP] = {0.f, 0.f, 0.f, 0.f};
    {
        const float* krow = kbase + (size_t)lane * (NKV * D_);
        #pragma unroll
        for (int i = 0; i < D_ / 4; i++) {
            float4 kk = *(const float4*)(krow + i * 4);
            #pragma unroll
            for (int r = 0; r < NREP; r++) {
                const float* qr = &qs[g][r * D_ + i * 4];
                s[r] = fmaf(kk.x, qr[0], s[r]);
                s[r] = fmaf(kk.y, qr[1], s[r]);
                s[r] = fmaf(kk.z, qr[2], s[r]);
                s[r] = fmaf(kk.w, qr[3], s[r]);
            }
        }
    }
    const float scale = 0.08838834764831845f;

    #pragma unroll
    for (int r = 0; r < NREP; r++) {
        float sc = s[r] * scale;
        float m = sc;
        #pragma unroll
        for (int o = 16; o > 0; o >>= 1)
            m = fmaxf(m, __shfl_xor_sync(0xFFFFFFFFu, m, o));
        float e = expf(sc - m);
        float sum = e;
        #pragma unroll
        for (int o = 16; o > 0; o >>= 1)
            sum += __shfl_xor_sync(0xFFFFFFFFu, sum, o);
        ws[g][r][lane] = e / sum;
    }
    __syncwarp();

    float4 acc[NREP];
    #pragma unroll
    for (int r = 0; r < NREP; r++) acc[r] = make_float4(0.f, 0.f, 0.f, 0.f);

    #pragma unroll 8
    for (int key = 0; key < KLAT; key++) {
        float4 vv = *(const float4*)(vbase + (size_t)key * (NKV * D_) + lane * 4);
        #pragma unroll
        for (int r = 0; r < NREP; r++) {
            float w = ws[g][r][key];
            acc[r].x = fmaf(w, vv.x, acc[r].x);
            acc[r].y = fmaf(w, vv.y, acc[r].y);
            acc[r].z = fmaf(w, vv.z, acc[r].z);
            acc[r].w = fmaf(w, vv.w, acc[r].w);
        }
    }

    float* ybase = y + (size_t)bt * C_ + g * (NREP * D_);
    #pragma unroll
    for (int r = 0; r < NREP; r++)
        *(float4*)(ybase + r * D_ + lane * 4) = acc[r];
}

// ---------------------------------------------------------------------------
// Launch. Inputs: x, channel_states, channel_mask, Wq, Wk, Wv, Wo, gate.
// ---------------------------------------------------------------------------
extern "C" void kernel_launch(void* const* d_in, const int* in_sizes, int n_in,
                              void* d_out, int out_size)
{
    const float* x    = (const float*)d_in[0];
    const float* cs   = (const float*)d_in[1];
    const int*   mask = (const int*)d_in[2];
    const float* Wq   = (const float*)d_in[3];
    const float* Wk   = (const float*)d_in[4];
    const float* Wv   = (const float*)d_in[5];
    const float* Wo   = (const float*)d_in[6];
    const float* gate = (const float*)d_in[7];
    float* out = (float*)d_out;

    float *q, *y, *kk, *vv, *part, *xA, *csA, *yA, *WqB, *WkB, *WvB, *WoB;
    cudaGetSymbolAddress((void**)&q,    g_q);
    cudaGetSymbolAddress((void**)&y,    g_y);
    cudaGetSymbolAddress((void**)&kk,   g_k);
    cudaGetSymbolAddress((void**)&vv,   g_v);
    cudaGetSymbolAddress((void**)&part, g_part);
    cudaGetSymbolAddress((void**)&xA,   g_xA);
    cudaGetSymbolAddress((void**)&csA,  g_csA);
    cudaGetSymbolAddress((void**)&yA,   g_yA);
    cudaGetSymbolAddress((void**)&WqB,  g_WqB);
    cudaGetSymbolAddress((void**)&WkB,  g_WkB);
    cudaGetSymbolAddress((void**)&WvB,  g_WvB);
    cudaGetSymbolAddress((void**)&WoB,  g_WoB);

    cudaFuncSetAttribute(mma_gemm_kernel,
                         cudaFuncAttributeMaxDynamicSharedMemorySize, GEMM_SMEM);

    const int M1  = B_ * T_;          // 2048
    const int Mkv = B_ * NCH * KLAT;  // 512
    const int Nkv = NKV * D_;         // 512

    // Reformat operands to fragment order (tf32-rounded).
    // Launch order matters: launch #5 (0-based) is the Q GEMM -> ncu captures it.
    reformat_A_kernel<<<(M1 * C_) / 1024, 256>>>(x,  xA,  C_);        // 0
    reformat_B_kernel<<<(C_ * C_) / 512, 256>>>(Wq, WqB, C_, C_);     // 1
    reformat_A_kernel<<<(Mkv * C_) / 1024, 256>>>(cs, csA, C_);       // 2
    reformat_B_kernel<<<(C_ * Nkv) / 512, 256>>>(Wk, WkB, C_, Nkv);   // 3
    reformat_B_kernel<<<(C_ * Nkv) / 512, 256>>>(Wv, WvB, C_, Nkv);   // 4

    // Q projection: (2048x2048) @ (2048x2048)                        // 5
    mma_gemm_kernel<<<dim3(C_ / BN, M1 / BM, 1), 256, GEMM_SMEM>>>(
        xA, WqB, q, M1, C_, C_, C_, nullptr);

    // K/V projections: (512x2048) @ (2048x512), split-K=8 + reduction
    mma_gemm_kernel<<<dim3(Nkv / BN, Mkv / BM, KV_SPLIT), 256, GEMM_SMEM>>>(
        csA, WkB, part, Mkv, Nkv, C_, C_ / KV_SPLIT, nullptr);
    reduce_split_kernel<<<(Mkv * Nkv) / 1024, 256>>>(part, kk, Mkv * Nkv);
    mma_gemm_kernel<<<dim3(Nkv / BN, Mkv / BM, KV_SPLIT), 256, GEMM_SMEM>>>(
        csA, WvB, part, Mkv, Nkv, C_, C_ / KV_SPLIT, nullptr);
    reduce_split_kernel<<<(Mkv * Nkv) / 1024, 256>>>(part, vv, Mkv * Nkv);

    // Attention
    attn_kernel<<<B_ * T_, 128>>>(q, kk, vv, mask, y);

    // Reformat y and Wo, then output projection + tanh(gate)
    reformat_A_kernel<<<(M1 * C_) / 1024, 256>>>(y, yA, C_);
    reformat_B_kernel<<<(C_ * C_) / 512, 256>>>(Wo, WoB, C_, C_);
    mma_gemm_kernel<<<dim3(C_ / BN, M1 / BM, 1), 256, GEMM_SMEM>>>(
        yA, WoB, out, M1, C_, C_, C_, gate);
}

// round 10
// speedup vs baseline: 7.0454x; 1.4974x over previous
#include <cuda_runtime.h>
#include <cuda_fp16.h>
#include <math.h>
#include <cstdint>

// ---------------------------------------------------------------------------
// Problem constants
// ---------------------------------------------------------------------------
#define B_   2
#define T_   1024
#define C_   2048
#define NCH  8
#define KLAT 32
#define NKV  4
#define NREP 4
#define D_   128

#define KV_SPLIT 8

// Scratch (device globals; allocation is forbidden)
__device__ float  g_q[B_ * T_ * C_];                 // 16 MB
__device__ float  g_y[B_ * T_ * C_];                 // 16 MB
__device__ float  g_k[B_ * NCH * KLAT * NKV * D_];   // 1 MB
__device__ float  g_v[B_ * NCH * KLAT * NKV * D_];   // 1 MB
__device__ float  g_part[KV_SPLIT * 512 * 512];      // 8 MB split-K partials
// Fragment-order fp16 operands (round-to-nearest; mma accumulates in fp32)
__device__ __half g_xA [B_ * T_ * C_];               // 8 MB
__device__ __half g_csA[B_ * NCH * KLAT * C_];       // 2 MB
__device__ __half g_yA [B_ * T_ * C_];               // 8 MB
__device__ __half g_WqB[C_ * C_];                    // 8 MB
__device__ __half g_WkB[C_ * NKV * D_];              // 2 MB
__device__ __half g_WvB[C_ * NKV * D_];              // 2 MB
__device__ __half g_WoB[C_ * C_];                    // 8 MB

// ---------------------------------------------------------------------------
// Helpers
// ---------------------------------------------------------------------------
__device__ __forceinline__ uint32_t smem_u32(const void* p) {
    uint32_t a;
    asm("{ .reg .u64 t; cvta.to.shared.u64 t, %1; cvt.u32.u64 %0, t; }"
        : "=r"(a) : "l"(p));
    return a;
}

__device__ __forceinline__ uint32_t pack_h2(float a, float b) {
    __half2 h = __halves2half2(__float2half_rn(a), __float2half_rn(b));
    return *(uint32_t*)&h;
}

// ---------------------------------------------------------------------------
// Reformat A: fp32 [M,K] row-major -> fp16 fragment order (m16n8k16).
// K-chunk = 64. Unit u = 16B = regs a0..a3 (8 fp16) of (rb, c, t, s, lane):
//   u = ((rb*nch + c)*32 + t*4 + s)*32 + lane,  nch = K/64
//   a0=(row g,   k0,k0+1) a1=(row g+8, k0,k0+1)
//   a2=(row g,   k0+8,+9) a3=(row g+8, k0+8,+9),  k0 = c*64+s*16+2*tig
// ---------------------------------------------------------------------------
__global__ void __launch_bounds__(256) reformat_A_kernel(
    const float* __restrict__ src, __half* __restrict__ dst, int K)
{
    int u = blockIdx.x * 256 + threadIdx.x;      // total units = M*K/8
    int lane = u & 31;
    int ts   = (u >> 5) & 31;                    // t*4+s
    int t    = ts >> 2, s = ts & 3;
    int nch  = K >> 6;
    int cu   = u >> 10;                          // rb*nch + c
    int c    = cu % nch;
    int rb   = cu / nch;
    int g    = lane >> 2, tig = lane & 3;
    int row  = rb * 128 + t * 16 + g;
    int k    = c * 64 + s * 16 + 2 * tig;

    const float* p0 = src + (size_t)row * K + k;
    const float* p1 = src + (size_t)(row + 8) * K + k;
    uint4 o;
    o.x = pack_h2(p0[0], p0[1]);   // a0
    o.y = pack_h2(p1[0], p1[1]);   // a1
    o.z = pack_h2(p0[8], p0[9]);   // a2
    o.w = pack_h2(p1[8], p1[9]);   // a3
    *(uint4*)(dst + (size_t)u * 8) = o;
}

// ---------------------------------------------------------------------------
// Reformat B: fp32 [K,N] row-major -> fp16 fragment order (m16n8k16).
// Unit u = 8B = regs b0,b1 (4 fp16) of (nb, c, nt, s, lane):
//   u = ((nb*nch + c)*128 + nt*4 + s)*32 + lane
//   b0=(k0,k0+1 ; n) b1=(k0+8,+9 ; n), k0=c*64+s*16+2*tig, n=nb*256+nt*8+g
// ---------------------------------------------------------------------------
__global__ void __launch_bounds__(256) reformat_B_kernel(
    const float* __restrict__ src, __half* __restrict__ dst, int K, int N)
{
    int u = blockIdx.x * 256 + threadIdx.x;      // total units = K*N/4
    int lane = u & 31;
    int nts  = (u >> 5) & 127;                   // nt*4+s
    int s    = nts & 3, nt = nts >> 2;
    int nch  = K >> 6;
    int cu   = u >> 12;                          // nb*nch + c
    int c    = cu % nch;
    int nb   = cu / nch;
    int g    = lane >> 2, tig = lane & 3;
    int k    = c * 64 + s * 16 + 2 * tig;
    int n    = nb * 256 + nt * 8 + g;

    uint2 o;
    o.x = pack_h2(src[(size_t)k * N + n], src[(size_t)(k + 1) * N + n]);
    o.y = pack_h2(src[(size_t)(k + 8) * N + n], src[(size_t)(k + 9) * N + n]);
    *(uint2*)(dst + (size_t)u * 4) = o;
}

// ---------------------------------------------------------------------------
// fp16 mma.sync GEMM (fp32 accumulate) on fragment-order operands.
// Block tile 128x256, 8 warps (2m x 4n), warp tile 64x64, K-chunk 64.
// 4-stage cp.async pipeline; chunk blocks contiguous in gmem.
// Fragment loads: LDS.128 (A) / LDS.64 (B), conflict-free.
// Split-K via blockIdx.z (k_len per z, multiple of 64).
// ---------------------------------------------------------------------------
#define BM 128
#define BN 256
#define STAGES 4
#define A_BYTES (BM * 64 * 2)                  // 16384 per chunk
#define B_BYTES (BN * 64 * 2)                  // 32768 per chunk
#define STAGE_BYTES (A_BYTES + B_BYTES)        // 49152
#define GEMM_SMEM (STAGES * STAGE_BYTES)       // 196608

__global__ void __launch_bounds__(256, 1) mma_gemm_kernel(
    const __half* __restrict__ Afrag, const __half* __restrict__ Bfrag,
    float* __restrict__ Cout, int M, int N, int K, int k_len,
    const float* __restrict__ scale_ptr)
{
    extern __shared__ char smem[];
    const uint32_t s_base = smem_u32(smem);

    const int tid    = threadIdx.x;
    const int lane   = tid & 31;
    const int wid    = tid >> 5;
    const int warp_m = wid & 1;
    const int warp_n = wid >> 1;

    const int rb  = blockIdx.y;
    const int nb  = blockIdx.x;
    const int z   = blockIdx.z;
    const int nchK = K >> 6;
    const int kc0 = z * (k_len >> 6);
    const int nch = k_len >> 6;
    float* outp = Cout + (size_t)z * M * N;

    const __half* AC = Afrag + (size_t)rb * nchK * 8192;   // halfs per chunk
    const __half* BC = Bfrag + (size_t)nb * nchK * 16384;

    auto issue = [&](int chunk, int buf) {
        uint32_t sb = s_base + buf * STAGE_BYTES;
        const __half* ga = AC + (size_t)(kc0 + chunk) * 8192;
        const __half* gb = BC + (size_t)(kc0 + chunk) * 16384;
        #pragma unroll
        for (int j = 0; j < 4; j++)
            asm volatile("cp.async.cg.shared.global [%0], [%1], 16;"
                :: "r"(sb + (tid + j * 256) * 16), "l"(ga + (tid + j * 256) * 8));
        #pragma unroll
        for (int j = 0; j < 8; j++)
            asm volatile("cp.async.cg.shared.global [%0], [%1], 16;"
                :: "r"(sb + A_BYTES + (tid + j * 256) * 16),
                   "l"(gb + (tid + j * 256) * 8));
        asm volatile("cp.async.commit_group;" ::: "memory");
    };

    float acc[4][8][4];
    #pragma unroll
    for (int a = 0; a < 4; a++)
        #pragma unroll
        for (int b = 0; b < 8; b++)
            #pragma unroll
            for (int c = 0; c < 4; c++) acc[a][b][c] = 0.0f;

    const int npro = (STAGES - 1 < nch) ? (STAGES - 1) : nch;
    for (int p = 0; p < npro; p++) issue(p, p % STAGES);

    for (int i = 0; i < nch; i++) {
        asm volatile("cp.async.wait_group %0;" :: "n"(STAGES - 2) : "memory");
        __syncthreads();

        const uint32_t ab = s_base + (i % STAGES) * STAGE_BYTES;
        const uint32_t bb = ab + A_BYTES;

        #pragma unroll
        for (int s = 0; s < 4; s++) {
            uint32_t areg[4][4];
            #pragma unroll
            for (int mt = 0; mt < 4; mt++) {
                int t = warp_m * 4 + mt;
                uint32_t addr = ab + ((t * 4 + s) * 32 + lane) * 16;
                asm volatile("ld.shared.v4.b32 {%0,%1,%2,%3}, [%4];"
                    : "=r"(areg[mt][0]), "=r"(areg[mt][1]),
                      "=r"(areg[mt][2]), "=r"(areg[mt][3])
                    : "r"(addr));
            }
            uint32_t breg[8][2];
            #pragma unroll
            for (int nt8 = 0; nt8 < 8; nt8++) {
                int nt = warp_n * 8 + nt8;
                uint32_t addr = bb + ((nt * 4 + s) * 32 + lane) * 8;
                asm volatile("ld.shared.v2.b32 {%0,%1}, [%2];"
                    : "=r"(breg[nt8][0]), "=r"(breg[nt8][1])
                    : "r"(addr));
            }
            #pragma unroll
            for (int mt = 0; mt < 4; mt++)
                #pragma unroll
                for (int nt8 = 0; nt8 < 8; nt8++)
                    asm volatile(
                        "mma.sync.aligned.m16n8k16.row.col.f32.f16.f16.f32 "
                        "{%0,%1,%2,%3}, {%4,%5,%6,%7}, {%8,%9}, {%0,%1,%2,%3};"
                        : "+f"(acc[mt][nt8][0]), "+f"(acc[mt][nt8][1]),
                          "+f"(acc[mt][nt8][2]), "+f"(acc[mt][nt8][3])
                        : "r"(areg[mt][0]), "r"(areg[mt][1]),
                          "r"(areg[mt][2]), "r"(areg[mt][3]),
                          "r"(breg[nt8][0]), "r"(breg[nt8][1]));
        }

        if (i + STAGES - 1 < nch)
            issue(i + STAGES - 1, (i + STAGES - 1) % STAGES);
    }

    // Epilogue
    float scale = 1.0f;
    if (scale_ptr) scale = tanhf(*scale_ptr);
    const int m0 = rb * BM, n0 = nb * BN;
    const int g = lane >> 2, tig = lane & 3;
    #pragma unroll
    for (int mt = 0; mt < 4; mt++) {
        int row = m0 + warp_m * 64 + mt * 16 + g;
        #pragma unroll
        for (int nt8 = 0; nt8 < 8; nt8++) {
            int col = n0 + warp_n * 64 + nt8 * 8 + 2 * tig;
            float2 v0, v1;
            v0.x = acc[mt][nt8][0] * scale; v0.y = acc[mt][nt8][1] * scale;
            v1.x = acc[mt][nt8][2] * scale; v1.y = acc[mt][nt8][3] * scale;
            *(float2*)(outp + (size_t)row * N + col) = v0;
            *(float2*)(outp + (size_t)(row + 8) * N + col) = v1;
        }
    }
}

// ---------------------------------------------------------------------------
// Deterministic split-K reduction: out[i] = sum_z part[z][i]
// ---------------------------------------------------------------------------
__global__ void __launch_bounds__(256) reduce_split_kernel(
    const float* __restrict__ part, float* __restrict__ out, int n)
{
    int i = (blockIdx.x * 256 + threadIdx.x) * 4;
    if (i < n) {
        float4 s = *(const float4*)(part + i);
        #pragma unroll
        for (int zz = 1; zz < KV_SPLIT; zz++) {
            float4 p = *(const float4*)(part + (size_t)zz * n + i);
            s.x += p.x; s.y += p.y; s.z += p.z; s.w += p.w;
        }
        *(float4*)(out + i) = s;
    }
}

// ---------------------------------------------------------------------------
// Tiny-K attention (known-good). One block per token, 128 threads.
// ---------------------------------------------------------------------------
__global__ void __launch_bounds__(128) attn_kernel(
    const float* __restrict__ q, const float* __restrict__ k,
    const float* __restrict__ v, const int* __restrict__ mask,
    float* __restrict__ y)
{
    const int bt   = blockIdx.x;
    const int b    = bt >> 10;
    const int g    = threadIdx.x >> 5;
    const int lane = threadIdx.x & 31;

    const int n = mask[bt];

    const size_t kv_chan = ((size_t)(b * NCH + n)) * KLAT * (NKV * D_);
    const float* kbase = k + kv_chan + g * D_;
    const float* vbase = v + kv_chan + g * D_;
    const float* qbase = q + (size_t)bt * C_ + g * (NREP * D_);

    __shared__ float qs[4][NREP * D_];
    __shared__ float ws[4][NREP][KLAT];

    {
        float4* dst = (float4*)&qs[g][0];
        const float4* src = (const float4*)qbase;
        #pragma unroll
        for (int i = 0; i < 4; i++) dst[i * 32 + lane] = src[i * 32 + lane];
    }
    __syncwarp();

    float s[NREP] = {0.f, 0.f, 0.f, 0.f};
    {
        const float* krow = kbase + (size_t)lane * (NKV * D_);
        #pragma unroll
        for (int i = 0; i < D_ / 4; i++) {
            float4 kk = *(const float4*)(krow + i * 4);
            #pragma unroll
            for (int r = 0; r < NREP; r++) {
                const float* qr = &qs[g][r * D_ + i * 4];
                s[r] = fmaf(kk.x, qr[0], s[r]);
                s[r] = fmaf(kk.y, qr[1], s[r]);
                s[r] = fmaf(kk.z, qr[2], s[r]);
                s[r] = fmaf(kk.w, qr[3], s[r]);
            }
        }
    }
    const float scale = 0.08838834764831845f;

    #pragma unroll
    for (int r = 0; r < NREP; r++) {
        float sc = s[r] * scale;
        float m = sc;
        #pragma unroll
        for (int o = 16; o > 0; o >>= 1)
            m = fmaxf(m, __shfl_xor_sync(0xFFFFFFFFu, m, o));
        float e = expf(sc - m);
        float sum = e;
        #pragma unroll
        for (int o = 16; o > 0; o >>= 1)
            sum += __shfl_xor_sync(0xFFFFFFFFu, sum, o);
        ws[g][r][lane] = e / sum;
    }
    __syncwarp();

    float4 acc[NREP];
    #pragma unroll
    for (int r = 0; r < NREP; r++) acc[r] = make_float4(0.f, 0.f, 0.f, 0.f);

    #pragma unroll 8
    for (int key = 0; key < KLAT; key++) {
        float4 vv = *(const float4*)(vbase + (size_t)key * (NKV * D_) + lane * 4);
        #pragma unroll
        for (int r = 0; r < NREP; r++) {
            float w = ws[g][r][key];
            acc[r].x = fmaf(w, vv.x, acc[r].x);
            acc[r].y = fmaf(w, vv.y, acc[r].y);
            acc[r].z = fmaf(w, vv.z, acc[r].z);
            acc[r].w = fmaf(w, vv.w, acc[r].w);
        }
    }

    float* ybase = y + (size_t)bt * C_ + g * (NREP * D_);
    #pragma unroll
    for (int r = 0; r < NREP; r++)
        *(float4*)(ybase + r * D_ + lane * 4) = acc[r];
}

// ---------------------------------------------------------------------------
// Launch. Inputs: x, channel_states, channel_mask, Wq, Wk, Wv, Wo, gate.
// ---------------------------------------------------------------------------
extern "C" void kernel_launch(void* const* d_in, const int* in_sizes, int n_in,
                              void* d_out, int out_size)
{
    const float* x    = (const float*)d_in[0];
    const float* cs   = (const float*)d_in[1];
    const int*   mask = (const int*)d_in[2];
    const float* Wq   = (const float*)d_in[3];
    const float* Wk   = (const float*)d_in[4];
    const float* Wv   = (const float*)d_in[5];
    const float* Wo   = (const float*)d_in[6];
    const float* gate = (const float*)d_in[7];
    float* out = (float*)d_out;

    float *q, *y, *kk, *vv, *part;
    __half *xA, *csA, *yA, *WqB, *WkB, *WvB, *WoB;
    cudaGetSymbolAddress((void**)&q,    g_q);
    cudaGetSymbolAddress((void**)&y,    g_y);
    cudaGetSymbolAddress((void**)&kk,   g_k);
    cudaGetSymbolAddress((void**)&vv,   g_v);
    cudaGetSymbolAddress((void**)&part, g_part);
    cudaGetSymbolAddress((void**)&xA,   g_xA);
    cudaGetSymbolAddress((void**)&csA,  g_csA);
    cudaGetSymbolAddress((void**)&yA,   g_yA);
    cudaGetSymbolAddress((void**)&WqB,  g_WqB);
    cudaGetSymbolAddress((void**)&WkB,  g_WkB);
    cudaGetSymbolAddress((void**)&WvB,  g_WvB);
    cudaGetSymbolAddress((void**)&WoB,  g_WoB);

    cudaFuncSetAttribute(mma_gemm_kernel,
                         cudaFuncAttributeMaxDynamicSharedMemorySize, GEMM_SMEM);

    const int M1  = B_ * T_;          // 2048
    const int Mkv = B_ * NCH * KLAT;  // 512
    const int Nkv = NKV * D_;         // 512

    // Reformat to fp16 fragment order. Q GEMM is OUR launch idx 4 so ncu
    // (-s 5, +1 for the harness d_out memset) captures the big GEMM.
    reformat_A_kernel<<<(M1 * C_) / 2048, 256>>>(x,  xA,  C_);        // 0
    reformat_B_kernel<<<(C_ * C_) / 1024, 256>>>(Wq, WqB, C_, C_);    // 1
    reformat_A_kernel<<<(Mkv * C_) / 2048, 256>>>(cs, csA, C_);       // 2
    reformat_B_kernel<<<(C_ * Nkv) / 1024, 256>>>(Wk, WkB, C_, Nkv);  // 3

    // Q projection: (2048x2048) @ (2048x2048)                        // 4
    mma_gemm_kernel<<<dim3(C_ / BN, M1 / BM, 1), 256, GEMM_SMEM>>>(
        xA, WqB, q, M1, C_, C_, C_, nullptr);

    reformat_B_kernel<<<(C_ * Nkv) / 1024, 256>>>(Wv, WvB, C_, Nkv);  // 5

    // K/V projections: (512x2048) @ (2048x512), split-K=8 + reduction
    mma_gemm_kernel<<<dim3(Nkv / BN, Mkv / BM, KV_SPLIT), 256, GEMM_SMEM>>>(
        csA, WkB, part, Mkv, Nkv, C_, C_ / KV_SPLIT, nullptr);
    reduce_split_kernel<<<(Mkv * Nkv) / 1024, 256>>>(part, kk, Mkv * Nkv);
    mma_gemm_kernel<<<dim3(Nkv / BN, Mkv / BM, KV_SPLIT), 256, GEMM_SMEM>>>(
        csA, WvB, part, Mkv, Nkv, C_, C_ / KV_SPLIT, nullptr);
    reduce_split_kernel<<<(Mkv * Nkv) / 1024, 256>>>(part, vv, Mkv * Nkv);

    // Attention
    attn_kernel<<<B_ * T_, 128>>>(q, kk, vv, mask, y);

    // Reformat y and Wo, then output projection + tanh(gate)
    reformat_A_kernel<<<(M1 * C_) / 2048, 256>>>(y, yA, C_);
    reformat_B_kernel<<<(C_ * C_) / 1024, 256>>>(Wo, WoB, C_, C_);
    mma_gemm_kernel<<<dim3(C_ / BN, M1 / BM, 1), 256, GEMM_SMEM>>>(
        yA, WoB, out, M1, C_, C_, C_, gate);
}

// round 12
// speedup vs baseline: 7.4090x; 1.0516x over previous
#include <cuda_runtime.h>
#include <cuda_fp16.h>
#include <math.h>
#include <cstdint>

// ---------------------------------------------------------------------------
// Problem constants
// ---------------------------------------------------------------------------
#define B_   2
#define T_   1024
#define C_   2048
#define NCH  8
#define KLAT 32
#define NKV  4
#define NREP 4
#define D_   128

#define KV_SPLIT 8
#define SPLITS  9          // attn token-list splits: 16*9 = 144 blocks ~ 1 wave

// Scratch (device globals; allocation is forbidden)
__device__ float  g_q[B_ * T_ * C_];                 // 16 MB
__device__ float  g_y[B_ * T_ * C_];                 // 16 MB
__device__ float  g_k[B_ * NCH * KLAT * NKV * D_];   // 1 MB
__device__ float  g_v[B_ * NCH * KLAT * NKV * D_];   // 1 MB
__device__ float  g_part[KV_SPLIT * 512 * 512];      // 8 MB split-K partials
__device__ int    g_list[B_ * NCH * T_];             // token lists per channel
__device__ int    g_cnt[B_ * NCH];
// Fragment-order fp16 operands (round-to-nearest; mma accumulates in fp32)
__device__ __half g_xA [B_ * T_ * C_];               // 8 MB
__device__ __half g_csA[B_ * NCH * KLAT * C_];       // 2 MB
__device__ __half g_yA [B_ * T_ * C_];               // 8 MB
__device__ __half g_WqB[C_ * C_];                    // 8 MB
__device__ __half g_WkB[C_ * NKV * D_];              // 2 MB
__device__ __half g_WvB[C_ * NKV * D_];              // 2 MB
__device__ __half g_WoB[C_ * C_];                    // 8 MB

// ---------------------------------------------------------------------------
// Helpers
// ---------------------------------------------------------------------------
__device__ __forceinline__ uint32_t smem_u32(const void* p) {
    uint32_t a;
    asm("{ .reg .u64 t; cvta.to.shared.u64 t, %1; cvt.u32.u64 %0, t; }"
        : "=r"(a) : "l"(p));
    return a;
}

__device__ __forceinline__ uint32_t pack_h2(float a, float b) {
    __half2 h = __halves2half2(__float2half_rn(a), __float2half_rn(b));
    return *(uint32_t*)&h;
}

// ---------------------------------------------------------------------------
// Reformat A: fp32 [M,K] row-major -> fp16 fragment order (m16n8k16).
// ---------------------------------------------------------------------------
__global__ void __launch_bounds__(256) reformat_A_kernel(
    const float* __restrict__ src, __half* __restrict__ dst, int K)
{
    int u = blockIdx.x * 256 + threadIdx.x;      // total units = M*K/8
    int lane = u & 31;
    int ts   = (u >> 5) & 31;                    // t*4+s
    int t    = ts >> 2, s = ts & 3;
    int nch  = K >> 6;
    int cu   = u >> 10;                          // rb*nch + c
    int c    = cu % nch;
    int rb   = cu / nch;
    int g    = lane >> 2, tig = lane & 3;
    int row  = rb * 128 + t * 16 + g;
    int k    = c * 64 + s * 16 + 2 * tig;

    const float* p0 = src + (size_t)row * K + k;
    const float* p1 = src + (size_t)(row + 8) * K + k;
    uint4 o;
    o.x = pack_h2(p0[0], p0[1]);   // a0
    o.y = pack_h2(p1[0], p1[1]);   // a1
    o.z = pack_h2(p0[8], p0[9]);   // a2
    o.w = pack_h2(p1[8], p1[9]);   // a3
    *(uint4*)(dst + (size_t)u * 8) = o;
}

// ---------------------------------------------------------------------------
// Reformat B: fp32 [K,N] row-major -> fp16 fragment order (m16n8k16).
// ---------------------------------------------------------------------------
__global__ void __launch_bounds__(256) reformat_B_kernel(
    const float* __restrict__ src, __half* __restrict__ dst, int K, int N)
{
    int u = blockIdx.x * 256 + threadIdx.x;      // total units = K*N/4
    int lane = u & 31;
    int nts  = (u >> 5) & 127;                   // nt*4+s
    int s    = nts & 3, nt = nts >> 2;
    int nch  = K >> 6;
    int cu   = u >> 12;                          // nb*nch + c
    int c    = cu % nch;
    int nb   = cu / nch;
    int g    = lane >> 2, tig = lane & 3;
    int k    = c * 64 + s * 16 + 2 * tig;
    int n    = nb * 256 + nt * 8 + g;

    uint2 o;
    o.x = pack_h2(src[(size_t)k * N + n], src[(size_t)(k + 1) * N + n]);
    o.y = pack_h2(src[(size_t)(k + 8) * N + n], src[(size_t)(k + 9) * N + n]);
    *(uint2*)(dst + (size_t)u * 4) = o;
}

// ---------------------------------------------------------------------------
// fp16 mma.sync GEMM (fp32 accumulate) on fragment-order operands.
// Block 128x256, 8 warps (2m x 4n), K-chunk 64, 4-stage cp.async pipeline.
// ---------------------------------------------------------------------------
#define BM 128
#define BN 256
#define STAGES 4
#define A_BYTES (BM * 64 * 2)                  // 16384 per chunk
#define B_BYTES (BN * 64 * 2)                  // 32768 per chunk
#define STAGE_BYTES (A_BYTES + B_BYTES)        // 49152
#define GEMM_SMEM (STAGES * STAGE_BYTES)       // 196608

__global__ void __launch_bounds__(256, 1) mma_gemm_kernel(
    const __half* __restrict__ Afrag, const __half* __restrict__ Bfrag,
    float* __restrict__ Cout, int M, int N, int K, int k_len,
    const float* __restrict__ scale_ptr)
{
    extern __shared__ char smem[];
    const uint32_t s_base = smem_u32(smem);

    const int tid    = threadIdx.x;
    const int lane   = tid & 31;
    const int wid    = tid >> 5;
    const int warp_m = wid & 1;
    const int warp_n = wid >> 1;

    const int rb  = blockIdx.y;
    const int nb  = blockIdx.x;
    const int z   = blockIdx.z;
    const int nchK = K >> 6;
    const int kc0 = z * (k_len >> 6);
    const int nch = k_len >> 6;
    float* outp = Cout + (size_t)z * M * N;

    const __half* AC = Afrag + (size_t)rb * nchK * 8192;
    const __half* BC = Bfrag + (size_t)nb * nchK * 16384;

    auto issue = [&](int chunk, int buf) {
        uint32_t sb = s_base + buf * STAGE_BYTES;
        const __half* ga = AC + (size_t)(kc0 + chunk) * 8192;
        const __half* gb = BC + (size_t)(kc0 + chunk) * 16384;
        #pragma unroll
        for (int j = 0; j < 4; j++)
            asm volatile("cp.async.cg.shared.global [%0], [%1], 16;"
                :: "r"(sb + (tid + j * 256) * 16), "l"(ga + (tid + j * 256) * 8));
        #pragma unroll
        for (int j = 0; j < 8; j++)
            asm volatile("cp.async.cg.shared.global [%0], [%1], 16;"
                :: "r"(sb + A_BYTES + (tid + j * 256) * 16),
                   "l"(gb + (tid + j * 256) * 8));
        asm volatile("cp.async.commit_group;" ::: "memory");
    };

    float acc[4][8][4];
    #pragma unroll
    for (int a = 0; a < 4; a++)
        #pragma unroll
        for (int b = 0; b < 8; b++)
            #pragma unroll
            for (int c = 0; c < 4; c++) acc[a][b][c] = 0.0f;

    const int npro = (STAGES - 1 < nch) ? (STAGES - 1) : nch;
    for (int p = 0; p < npro; p++) issue(p, p % STAGES);

    for (int i = 0; i < nch; i++) {
        asm volatile("cp.async.wait_group %0;" :: "n"(STAGES - 2) : "memory");
        __syncthreads();

        const uint32_t ab = s_base + (i % STAGES) * STAGE_BYTES;
        const uint32_t bb = ab + A_BYTES;

        #pragma unroll
        for (int s = 0; s < 4; s++) {
            uint32_t areg[4][4];
            #pragma unroll
            for (int mt = 0; mt < 4; mt++) {
                int t = warp_m * 4 + mt;
                uint32_t addr = ab + ((t * 4 + s) * 32 + lane) * 16;
                asm volatile("ld.shared.v4.b32 {%0,%1,%2,%3}, [%4];"
                    : "=r"(areg[mt][0]), "=r"(areg[mt][1]),
                      "=r"(areg[mt][2]), "=r"(areg[mt][3])
                    : "r"(addr));
            }
            uint32_t breg[8][2];
            #pragma unroll
            for (int nt8 = 0; nt8 < 8; nt8++) {
                int nt = warp_n * 8 + nt8;
                uint32_t addr = bb + ((nt * 4 + s) * 32 + lane) * 8;
                asm volatile("ld.shared.v2.b32 {%0,%1}, [%2];"
                    : "=r"(breg[nt8][0]), "=r"(breg[nt8][1])
                    : "r"(addr));
            }
            #pragma unroll
            for (int mt = 0; mt < 4; mt++)
                #pragma unroll
                for (int nt8 = 0; nt8 < 8; nt8++)
                    asm volatile(
                        "mma.sync.aligned.m16n8k16.row.col.f32.f16.f16.f32 "
                        "{%0,%1,%2,%3}, {%4,%5,%6,%7}, {%8,%9}, {%0,%1,%2,%3};"
                        : "+f"(acc[mt][nt8][0]), "+f"(acc[mt][nt8][1]),
                          "+f"(acc[mt][nt8][2]), "+f"(acc[mt][nt8][3])
                        : "r"(areg[mt][0]), "r"(areg[mt][1]),
                          "r"(areg[mt][2]), "r"(areg[mt][3]),
                          "r"(breg[nt8][0]), "r"(breg[nt8][1]));
        }

        if (i + STAGES - 1 < nch)
            issue(i + STAGES - 1, (i + STAGES - 1) % STAGES);
    }

    // Epilogue
    float scale = 1.0f;
    if (scale_ptr) scale = tanhf(*scale_ptr);
    const int m0 = rb * BM, n0 = nb * BN;
    const int g = lane >> 2, tig = lane & 3;
    #pragma unroll
    for (int mt = 0; mt < 4; mt++) {
        int row = m0 + warp_m * 64 + mt * 16 + g;
        #pragma unroll
        for (int nt8 = 0; nt8 < 8; nt8++) {
            int col = n0 + warp_n * 64 + nt8 * 8 + 2 * tig;
            float2 v0, v1;
            v0.x = acc[mt][nt8][0] * scale; v0.y = acc[mt][nt8][1] * scale;
            v1.x = acc[mt][nt8][2] * scale; v1.y = acc[mt][nt8][3] * scale;
            *(float2*)(outp + (size_t)row * N + col) = v0;
            *(float2*)(outp + (size_t)(row + 8) * N + col) = v1;
        }
    }
}

// ---------------------------------------------------------------------------
// Deterministic split-K reduction: out[i] = sum_z part[z][i]
// ---------------------------------------------------------------------------
__global__ void __launch_bounds__(256) reduce_split_kernel(
    const float* __restrict__ part, float* __restrict__ out, int n)
{
    int i = (blockIdx.x * 256 + threadIdx.x) * 4;
    if (i < n) {
        float4 s = *(const float4*)(part + i);
        #pragma unroll
        for (int zz = 1; zz < KV_SPLIT; zz++) {
            float4 p = *(const float4*)(part + (size_t)zz * n + i);
            s.x += p.x; s.y += p.y; s.z += p.z; s.w += p.w;
        }
        *(float4*)(out + i) = s;
    }
}

// ---------------------------------------------------------------------------
// Build per-(batch,channel) token lists. Grid = B_, block = T_ threads.
// List order within a channel is non-deterministic (atomics) but the per-
// token attention output does not depend on list order.
// ---------------------------------------------------------------------------
__global__ void __launch_bounds__(T_) build_lists_kernel(
    const int* __restrict__ mask, int* __restrict__ list, int* __restrict__ cnt)
{
    __shared__ int scnt[NCH];
    const int b = blockIdx.x;
    if (threadIdx.x < NCH) scnt[threadIdx.x] = 0;
    __syncthreads();
    const int t = threadIdx.x;
    const int n = mask[b * T_ + t];
    const int pos = atomicAdd(&scnt[n], 1);
    list[(b * NCH + n) * T_ + pos] = t;
    __syncthreads();
    if (threadIdx.x < NCH) cnt[b * NCH + threadIdx.x] = scnt[threadIdx.x];
}

// ---------------------------------------------------------------------------
// Channel-grouped attention. Block = (channel bn, split sp). 256 threads
// = 8 warps: sub = wid>>2 selects one of 2 concurrent tokens, g = wid&3 the
// kv group. Stage channel K transposed (Kt[g][d][key], pad 33) and V
// (natural layout) in dynamic smem once; loop over the channel's tokens.
// All operand reads in the token loop are conflict-free smem accesses.
// No block syncs inside the loop (warps fully independent).
// ---------------------------------------------------------------------------
#define KT_FLOATS (4 * 128 * 33)                       // 16896
#define VS_FLOATS (KLAT * 512)                         // 16384
#define QS_FLOATS (2 * 4 * NREP * D_)                  // 4096
#define WS_FLOATS (2 * 4 * NREP * KLAT)                // 512
#define ATTN_SMEM ((KT_FLOATS + VS_FLOATS + QS_FLOATS + WS_FLOATS) * 4)

__global__ void __launch_bounds__(256, 1) attn2_kernel(
    const float* __restrict__ q, const float* __restrict__ k,
    const float* __restrict__ v, float* __restrict__ y,
    const int* __restrict__ list, const int* __restrict__ cnt)
{
    extern __shared__ float sm[];
    float* Kt = sm;                                   // [g][d][key] pad 33
    float* Vs = Kt + KT_FLOATS;                       // [key][512]
    float* qs = Vs + VS_FLOATS;                       // [sub][g][512]
    float* ws = qs + QS_FLOATS;                       // [sub][g][r][32]

    const int bn   = blockIdx.x;                      // b*NCH + n
    const int b    = bn >> 3;
    const int sp   = blockIdx.y;
    const int tid  = threadIdx.x;
    const int wid  = tid >> 5;
    const int lane = tid & 31;
    const int sub  = wid >> 2;
    const int g    = wid & 3;

    // Stage K (transposed) and V
    const float* kch = k + (size_t)bn * KLAT * 512;
    const float* vch = v + (size_t)bn * KLAT * 512;
    for (int idx = tid; idx < KLAT * 512; idx += 256) {
        int key = idx >> 9, col = idx & 511;
        Kt[((col >> 7) * 128 + (col & 127)) * 33 + key] = kch[idx];
        Vs[idx] = vch[idx];
    }
    __syncthreads();

    const int   cnt_bn = cnt[bn];
    const int*  lst    = list + bn * T_;
    const float scale  = 0.08838834764831845f;        // 1/sqrt(128)

    float* qs_w = qs + (sub * 4 + g) * (NREP * D_);
    float* ws_w = ws + (sub * 4 + g) * (NREP * KLAT);
    const float* ktg = Kt + g * 128 * 33;
    const float* vsg = Vs + g * D_;

    for (int base = 2 * sp; base < cnt_bn; base += 2 * SPLITS) {
        const int ti = base + sub;
        if (ti >= cnt_bn) continue;
        const int t  = lst[ti];
        const int bt = b * T_ + t;

        // stage this token's q for group g (512 floats, 4 float4/lane)
        const float4* qsrc = (const float4*)(q + (size_t)bt * C_ + g * (NREP * D_));
        float4* qdst = (float4*)qs_w;
        #pragma unroll
        for (int i = 0; i < 4; i++) qdst[i * 32 + lane] = qsrc[i * 32 + lane];
        __syncwarp();

        // phase 1: lane = key; scores for 4 rep heads
        float s[NREP] = {0.f, 0.f, 0.f, 0.f};
        #pragma unroll 8
        for (int d4 = 0; d4 < D_; d4 += 4) {
            float kt0 = ktg[(d4 + 0) * 33 + lane];
            float kt1 = ktg[(d4 + 1) * 33 + lane];
            float kt2 = ktg[(d4 + 2) * 33 + lane];
            float kt3 = ktg[(d4 + 3) * 33 + lane];
            #pragma unroll
            for (int r = 0; r < NREP; r++) {
                const float4 qv = *(const float4*)(qs_w + r * D_ + d4);
                s[r] = fmaf(kt0, qv.x, s[r]);
                s[r] = fmaf(kt1, qv.y, s[r]);
                s[r] = fmaf(kt2, qv.z, s[r]);
                s[r] = fmaf(kt3, qv.w, s[r]);
            }
        }

        // phase 2: softmax over 32 keys
        #pragma unroll
        for (int r = 0; r < NREP; r++) {
            float sc = s[r] * scale;
            float m = sc;
            #pragma unroll
            for (int o = 16; o > 0; o >>= 1)
                m = fmaxf(m, __shfl_xor_sync(0xFFFFFFFFu, m, o));
            float e = expf(sc - m);
            float sum = e;
            #pragma unroll
            for (int o = 16; o > 0; o >>= 1)
                sum += __shfl_xor_sync(0xFFFFFFFFu, sum, o);
            ws_w[r * KLAT + lane] = e / sum;
        }
        __syncwarp();

        // phase 3: lane = d-chunk; accumulate over keys from smem V
        float4 acc[NREP];
        #pragma unroll
        for (int r = 0; r < NREP; r++) acc[r] = make_float4(0.f, 0.f, 0.f, 0.f);
        #pragma unroll 8
        for (int key = 0; key < KLAT; key++) {
            float4 vv = *(const float4*)(vsg + key * 512 + lane * 4);
            #pragma unroll
            for (int r = 0; r < NREP; r++) {
                float w = ws_w[r * KLAT + key];
                acc[r].x = fmaf(w, vv.x, acc[r].x);
                acc[r].y = fmaf(w, vv.y, acc[r].y);
                acc[r].z = fmaf(w, vv.z, acc[r].z);
                acc[r].w = fmaf(w, vv.w, acc[r].w);
            }
        }

        float* ybase = y + (size_t)bt * C_ + g * (NREP * D_);
        #pragma unroll
        for (int r = 0; r < NREP; r++)
            *(float4*)(ybase + r * D_ + lane * 4) = acc[r];
    }
}

// ---------------------------------------------------------------------------
// Launch. Inputs: x, channel_states, channel_mask, Wq, Wk, Wv, Wo, gate.
// ---------------------------------------------------------------------------
extern "C" void kernel_launch(void* const* d_in, const int* in_sizes, int n_in,
                              void* d_out, int out_size)
{
    const float* x    = (const float*)d_in[0];
    const float* cs   = (const float*)d_in[1];
    const int*   mask = (const int*)d_in[2];
    const float* Wq   = (const float*)d_in[3];
    const float* Wk   = (const float*)d_in[4];
    const float* Wv   = (const float*)d_in[5];
    const float* Wo   = (const float*)d_in[6];
    const float* gate = (const float*)d_in[7];
    float* out = (float*)d_out;

    float *q, *y, *kk, *vv, *part;
    int *list, *cnt;
    __half *xA, *csA, *yA, *WqB, *WkB, *WvB, *WoB;
    cudaGetSymbolAddress((void**)&q,    g_q);
    cudaGetSymbolAddress((void**)&y,    g_y);
    cudaGetSymbolAddress((void**)&kk,   g_k);
    cudaGetSymbolAddress((void**)&vv,   g_v);
    cudaGetSymbolAddress((void**)&part, g_part);
    cudaGetSymbolAddress((void**)&list, g_list);
    cudaGetSymbolAddress((void**)&cnt,  g_cnt);
    cudaGetSymbolAddress((void**)&xA,   g_xA);
    cudaGetSymbolAddress((void**)&csA,  g_csA);
    cudaGetSymbolAddress((void**)&yA,   g_yA);
    cudaGetSymbolAddress((void**)&WqB,  g_WqB);
    cudaGetSymbolAddress((void**)&WkB,  g_WkB);
    cudaGetSymbolAddress((void**)&WvB,  g_WvB);
    cudaGetSymbolAddress((void**)&WoB,  g_WoB);

    cudaFuncSetAttribute(mma_gemm_kernel,
                         cudaFuncAttributeMaxDynamicSharedMemorySize, GEMM_SMEM);
    cudaFuncSetAttribute(attn2_kernel,
                         cudaFuncAttributeMaxDynamicSharedMemorySize, ATTN_SMEM);

    const int M1  = B_ * T_;          // 2048
    const int Mkv = B_ * NCH * KLAT;  // 512
    const int Nkv = NKV * D_;         // 512

    // Token lists (independent of projections; do it first)
    build_lists_kernel<<<B_, T_>>>(mask, list, cnt);

    // Reformat to fp16 fragment order
    reformat_A_kernel<<<(M1 * C_) / 2048, 256>>>(x,  xA,  C_);
    reformat_B_kernel<<<(C_ * C_) / 1024, 256>>>(Wq, WqB, C_, C_);
    reformat_A_kernel<<<(Mkv * C_) / 2048, 256>>>(cs, csA, C_);

    // Q projection: (2048x2048) @ (2048x2048)
    mma_gemm_kernel<<<dim3(C_ / BN, M1 / BM, 1), 256, GEMM_SMEM>>>(
        xA, WqB, q, M1, C_, C_, C_, nullptr);

    reformat_B_kernel<<<(C_ * Nkv) / 1024, 256>>>(Wk, WkB, C_, Nkv);
    reformat_B_kernel<<<(C_ * Nkv) / 1024, 256>>>(Wv, WvB, C_, Nkv);

    // K/V projections: (512x2048) @ (2048x512), split-K=8 + reduction
    mma_gemm_kernel<<<dim3(Nkv / BN, Mkv / BM, KV_SPLIT), 256, GEMM_SMEM>>>(
        csA, WkB, part, Mkv, Nkv, C_, C_ / KV_SPLIT, nullptr);
    reduce_split_kernel<<<(Mkv * Nkv) / 1024, 256>>>(part, kk, Mkv * Nkv);
    mma_gemm_kernel<<<dim3(Nkv / BN, Mkv / BM, KV_SPLIT), 256, GEMM_SMEM>>>(
        csA, WvB, part, Mkv, Nkv, C_, C_ / KV_SPLIT, nullptr);
    reduce_split_kernel<<<(Mkv * Nkv) / 1024, 256>>>(part, vv, Mkv * Nkv);

    // Channel-grouped attention
    attn2_kernel<<<dim3(B_ * NCH, SPLITS), 256, ATTN_SMEM>>>(
        q, kk, vv, y, list, cnt);

    // Reformat y and Wo, then output projection + tanh(gate)
    reformat_A_kernel<<<(M1 * C_) / 2048, 256>>>(y, yA, C_);
    reformat_B_kernel<<<(C_ * C_) / 1024, 256>>>(Wo, WoB, C_, C_);
    mma_gemm_kernel<<<dim3(C_ / BN, M1 / BM, 1), 256, GEMM_SMEM>>>(
        yA, WoB, out, M1, C_, C_, C_, gate);
}

// round 14
// speedup vs baseline: 7.6556x; 1.0333x over previous
#include <cuda_runtime.h>
#include <cuda_fp16.h>
#include <math.h>
#include <cstdint>

// ---------------------------------------------------------------------------
// Problem constants
// ---------------------------------------------------------------------------
#define B_   2
#define T_   1024
#define C_   2048
#define NCH  8
#define KLAT 32
#define NKV  4
#define NREP 4
#define D_   128

#define KV_SPLIT 8
#define SPLITS  9          // attn token-list splits: 16*9 = 144 blocks ~ 1 wave

// Scratch (device globals; allocation is forbidden)
__device__ float  g_q[B_ * T_ * C_];                 // 16 MB
__device__ float  g_k[B_ * NCH * KLAT * NKV * D_];   // 1 MB
__device__ float  g_v[B_ * NCH * KLAT * NKV * D_];   // 1 MB
__device__ float  g_part[KV_SPLIT * 512 * 512];      // 8 MB split-K partials
__device__ int    g_list[B_ * NCH * T_];             // token lists per channel
__device__ int    g_cnt[B_ * NCH];
// Fragment-order fp16 operands
__device__ __half g_xA [B_ * T_ * C_];               // 8 MB
__device__ __half g_csA[B_ * NCH * KLAT * C_];       // 2 MB
__device__ __half g_yA [B_ * T_ * C_];               // 8 MB (written by attn2)
__device__ __half g_WqB[C_ * C_];                    // 8 MB
__device__ __half g_WkB[C_ * NKV * D_];              // 2 MB
__device__ __half g_WvB[C_ * NKV * D_];              // 2 MB
__device__ __half g_WoB[C_ * C_];                    // 8 MB

// ---------------------------------------------------------------------------
// Helpers
// ---------------------------------------------------------------------------
__device__ __forceinline__ uint32_t smem_u32(const void* p) {
    uint32_t a;
    asm("{ .reg .u64 t; cvta.to.shared.u64 t, %1; cvt.u32.u64 %0, t; }"
        : "=r"(a) : "l"(p));
    return a;
}

__device__ __forceinline__ uint32_t pack_h2(float a, float b) {
    __half2 h = __halves2half2(__float2half_rn(a), __float2half_rn(b));
    return *(uint32_t*)&h;
}

// ---------------------------------------------------------------------------
// Tiled reformat A: fp32 [M,K] row-major -> fp16 fragment order (m16n8k16).
// One block = one (128-row, 64-k) chunk. Coalesced float4 reads, smem
// scatter, contiguous 16 KB chunk write.
// Fragment map (within chunk): unit = (t*4+s)*32 + g8*4 + tig, uint32 slot
//  = khi*2 + rowbit;  row = t*16 + g8 + 8*rowbit;  k = s*16 + 2*tig + 8*khi.
// ---------------------------------------------------------------------------
__global__ void __launch_bounds__(256) reformat_A_tiled(
    const float* __restrict__ src, __half* __restrict__ dst, int K)
{
    __shared__ uint32_t su[4096];      // 16 KB = one A chunk
    const int tid = threadIdx.x;
    const int cB  = blockIdx.x;        // k-chunk (K/64)
    const int rb  = blockIdx.y;        // 128-row block
    const int nch = K >> 6;

    const float* s0 = src + (size_t)rb * 128 * K + cB * 64;
    #pragma unroll
    for (int j = 0; j < 8; j++) {
        int idx = tid + j * 256;                 // 2048 float4
        int row = idx >> 4, c4 = idx & 15;
        float4 v = *(const float4*)(s0 + (size_t)row * K + c4 * 4);
        int t = row >> 4, g8 = row & 7, rowbit = (row >> 3) & 1;
        int k4 = c4 * 4;                         // 0,4,...,60
        int s  = k4 >> 4;
        int km = k4 & 15;                        // 0,4,8,12
        int khi = km >> 3;
        int tig = (km & 7) >> 1;                 // 0 or 2
        int uu  = (t * 4 + s) * 32 + g8 * 4 + tig;
        int slot = (khi << 1) | rowbit;
        su[uu * 4 + slot]       = pack_h2(v.x, v.y);
        su[(uu + 1) * 4 + slot] = pack_h2(v.z, v.w);
    }
    __syncthreads();
    uint4* dout = (uint4*)(dst + ((size_t)rb * nch + cB) * 8192);
    const uint4* sin = (const uint4*)su;
    #pragma unroll
    for (int j = 0; j < 4; j++)
        dout[tid + j * 256] = sin[tid + j * 256];
}

// ---------------------------------------------------------------------------
// Tiled reformat B: fp32 [K,N] row-major -> fp16 fragment order.
// One block = (64-k chunk) x (128-n half-slice). Coalesced reads -> smem
// transpose (half, padded) -> contiguous 16 KB half-chunk write.
// ---------------------------------------------------------------------------
__global__ void __launch_bounds__(256) reformat_B_tiled(
    const float* __restrict__ src, __half* __restrict__ dst, int K, int N)
{
    __shared__ __half sh[64][136];     // 64 k x 128 n (+8 pad)
    const int tid = threadIdx.x;
    const int nslice = blockIdx.x;     // 128-n slice
    const int cB = blockIdx.y;         // k-chunk
    const int nch = K >> 6;
    const int nb = nslice >> 1, half = nslice & 1;
    const int n0 = nslice * 128;

    const float* s0 = src + (size_t)cB * 64 * N + n0;
    #pragma unroll
    for (int j = 0; j < 8; j++) {
        int idx = tid + j * 256;                 // 2048 float4
        int kr = idx >> 5, c4 = idx & 31;
        float4 v = *(const float4*)(s0 + (size_t)kr * N + c4 * 4);
        __half2 h01 = __halves2half2(__float2half_rn(v.x), __float2half_rn(v.y));
        __half2 h23 = __halves2half2(__float2half_rn(v.z), __float2half_rn(v.w));
        *(__half2*)&sh[kr][c4 * 4]     = h01;
        *(__half2*)&sh[kr][c4 * 4 + 2] = h23;
    }
    __syncthreads();

    uint2* dout = (uint2*)(dst + (((size_t)nb * nch + cB) * 4096 +
                                  (size_t)half * 2048) * 4);
    #pragma unroll
    for (int j = 0; j < 8; j++) {
        int o = tid + j * 256;                   // 2048 uint2
        int lane2 = o & 31, grp = o >> 5;        // grp 0..63 (local)
        int s  = grp & 3;
        int ntl = grp >> 2;                      // 0..15 local nt
        int g8 = lane2 >> 2, tig = lane2 & 3;
        int nl = ntl * 8 + g8;                   // 0..127 within slice
        int kp = s * 16 + 2 * tig;
        uint32_t lo = (uint32_t)__half_as_ushort(sh[kp][nl]) |
                      ((uint32_t)__half_as_ushort(sh[kp + 1][nl]) << 16);
        uint32_t hi = (uint32_t)__half_as_ushort(sh[kp + 8][nl]) |
                      ((uint32_t)__half_as_ushort(sh[kp + 9][nl]) << 16);
        dout[o] = make_uint2(lo, hi);
    }
}

// ---------------------------------------------------------------------------
// fp16 mma.sync GEMM (fp32 accumulate) on fragment-order operands.
// Block 128x256, 8 warps (2m x 4n), K-chunk 64, 4-stage cp.async pipeline.
// ---------------------------------------------------------------------------
#define BM 128
#define BN 256
#define STAGES 4
#define A_BYTES (BM * 64 * 2)                  // 16384 per chunk
#define B_BYTES (BN * 64 * 2)                  // 32768 per chunk
#define STAGE_BYTES (A_BYTES + B_BYTES)        // 49152
#define GEMM_SMEM (STAGES * STAGE_BYTES)       // 196608

__global__ void __launch_bounds__(256, 1) mma_gemm_kernel(
    const __half* __restrict__ Afrag, const __half* __restrict__ Bfrag,
    float* __restrict__ Cout, int M, int N, int K, int k_len,
    const float* __restrict__ scale_ptr)
{
    extern __shared__ char smem[];
    const uint32_t s_base = smem_u32(smem);

    const int tid    = threadIdx.x;
    const int lane   = tid & 31;
    const int wid    = tid >> 5;
    const int warp_m = wid & 1;
    const int warp_n = wid >> 1;

    const int rb  = blockIdx.y;
    const int nb  = blockIdx.x;
    const int z   = blockIdx.z;
    const int nchK = K >> 6;
    const int kc0 = z * (k_len >> 6);
    const int nch = k_len >> 6;
    float* outp = Cout + (size_t)z * M * N;

    const __half* AC = Afrag + (size_t)rb * nchK * 8192;
    const __half* BC = Bfrag + (size_t)nb * nchK * 16384;

    auto issue = [&](int chunk, int buf) {
        uint32_t sb = s_base + buf * STAGE_BYTES;
        const __half* ga = AC + (size_t)(kc0 + chunk) * 8192;
        const __half* gb = BC + (size_t)(kc0 + chunk) * 16384;
        #pragma unroll
        for (int j = 0; j < 4; j++)
            asm volatile("cp.async.cg.shared.global [%0], [%1], 16;"
                :: "r"(sb + (tid + j * 256) * 16), "l"(ga + (tid + j * 256) * 8));
        #pragma unroll
        for (int j = 0; j < 8; j++)
            asm volatile("cp.async.cg.shared.global [%0], [%1], 16;"
                :: "r"(sb + A_BYTES + (tid + j * 256) * 16),
                   "l"(gb + (tid + j * 256) * 8));
        asm volatile("cp.async.commit_group;" ::: "memory");
    };

    float acc[4][8][4];
    #pragma unroll
    for (int a = 0; a < 4; a++)
        #pragma unroll
        for (int b = 0; b < 8; b++)
            #pragma unroll
            for (int c = 0; c < 4; c++) acc[a][b][c] = 0.0f;

    const int npro = (STAGES - 1 < nch) ? (STAGES - 1) : nch;
    for (int p = 0; p < npro; p++) issue(p, p % STAGES);

    for (int i = 0; i < nch; i++) {
        asm volatile("cp.async.wait_group %0;" :: "n"(STAGES - 2) : "memory");
        __syncthreads();

        const uint32_t ab = s_base + (i % STAGES) * STAGE_BYTES;
        const uint32_t bb = ab + A_BYTES;

        #pragma unroll
        for (int s = 0; s < 4; s++) {
            uint32_t areg[4][4];
            #pragma unroll
            for (int mt = 0; mt < 4; mt++) {
                int t = warp_m * 4 + mt;
                uint32_t addr = ab + ((t * 4 + s) * 32 + lane) * 16;
                asm volatile("ld.shared.v4.b32 {%0,%1,%2,%3}, [%4];"
                    : "=r"(areg[mt][0]), "=r"(areg[mt][1]),
                      "=r"(areg[mt][2]), "=r"(areg[mt][3])
                    : "r"(addr));
            }
            uint32_t breg[8][2];
            #pragma unroll
            for (int nt8 = 0; nt8 < 8; nt8++) {
                int nt = warp_n * 8 + nt8;
                uint32_t addr = bb + ((nt * 4 + s) * 32 + lane) * 8;
                asm volatile("ld.shared.v2.b32 {%0,%1}, [%2];"
                    : "=r"(breg[nt8][0]), "=r"(breg[nt8][1])
                    : "r"(addr));
            }
            #pragma unroll
            for (int mt = 0; mt < 4; mt++)
                #pragma unroll
                for (int nt8 = 0; nt8 < 8; nt8++)
                    asm volatile(
                        "mma.sync.aligned.m16n8k16.row.col.f32.f16.f16.f32 "
                        "{%0,%1,%2,%3}, {%4,%5,%6,%7}, {%8,%9}, {%0,%1,%2,%3};"
                        : "+f"(acc[mt][nt8][0]), "+f"(acc[mt][nt8][1]),
                          "+f"(acc[mt][nt8][2]), "+f"(acc[mt][nt8][3])
                        : "r"(areg[mt][0]), "r"(areg[mt][1]),
                          "r"(areg[mt][2]), "r"(areg[mt][3]),
                          "r"(breg[nt8][0]), "r"(breg[nt8][1]));
        }

        if (i + STAGES - 1 < nch)
            issue(i + STAGES - 1, (i + STAGES - 1) % STAGES);
    }

    // Epilogue
    float scale = 1.0f;
    if (scale_ptr) scale = tanhf(*scale_ptr);
    const int m0 = rb * BM, n0 = nb * BN;
    const int g = lane >> 2, tig = lane & 3;
    #pragma unroll
    for (int mt = 0; mt < 4; mt++) {
        int row = m0 + warp_m * 64 + mt * 16 + g;
        #pragma unroll
        for (int nt8 = 0; nt8 < 8; nt8++) {
            int col = n0 + warp_n * 64 + nt8 * 8 + 2 * tig;
            float2 v0, v1;
            v0.x = acc[mt][nt8][0] * scale; v0.y = acc[mt][nt8][1] * scale;
            v1.x = acc[mt][nt8][2] * scale; v1.y = acc[mt][nt8][3] * scale;
            *(float2*)(outp + (size_t)row * N + col) = v0;
            *(float2*)(outp + (size_t)(row + 8) * N + col) = v1;
        }
    }
}

// ---------------------------------------------------------------------------
// Deterministic split-K reduction: out[i] = sum_z part[z][i]
// ---------------------------------------------------------------------------
__global__ void __launch_bounds__(256) reduce_split_kernel(
    const float* __restrict__ part, float* __restrict__ out, int n)
{
    int i = (blockIdx.x * 256 + threadIdx.x) * 4;
    if (i < n) {
        float4 s = *(const float4*)(part + i);
        #pragma unroll
        for (int zz = 1; zz < KV_SPLIT; zz++) {
            float4 p = *(const float4*)(part + (size_t)zz * n + i);
            s.x += p.x; s.y += p.y; s.z += p.z; s.w += p.w;
        }
        *(float4*)(out + i) = s;
    }
}

// ---------------------------------------------------------------------------
// Build per-(batch,channel) token lists. Grid = B_, block = T_ threads.
// ---------------------------------------------------------------------------
__global__ void __launch_bounds__(T_) build_lists_kernel(
    const int* __restrict__ mask, int* __restrict__ list, int* __restrict__ cnt)
{
    __shared__ int scnt[NCH];
    const int b = blockIdx.x;
    if (threadIdx.x < NCH) scnt[threadIdx.x] = 0;
    __syncthreads();
    const int t = threadIdx.x;
    const int n = mask[b * T_ + t];
    const int pos = atomicAdd(&scnt[n], 1);
    list[(b * NCH + n) * T_ + pos] = t;
    __syncthreads();
    if (threadIdx.x < NCH) cnt[b * NCH + threadIdx.x] = scnt[threadIdx.x];
}

// ---------------------------------------------------------------------------
// Channel-grouped attention; writes yA DIRECTLY in fragment-A fp16 order.
// Block = (channel bn, split sp), 256 threads = 2 tokens x 4 kv-groups.
// ---------------------------------------------------------------------------
#define KT_FLOATS (4 * 128 * 33)                       // 16896
#define VS_FLOATS (KLAT * 512)                         // 16384
#define QS_FLOATS (2 * 4 * NREP * D_)                  // 4096
#define WS_FLOATS (2 * 4 * NREP * KLAT)                // 512
#define ATTN_SMEM ((KT_FLOATS + VS_FLOATS + QS_FLOATS + WS_FLOATS) * 4)

__global__ void __launch_bounds__(256, 1) attn2_kernel(
    const float* __restrict__ q, const float* __restrict__ k,
    const float* __restrict__ v, __half* __restrict__ yA,
    const int* __restrict__ list, const int* __restrict__ cnt)
{
    extern __shared__ float sm[];
    float* Kt = sm;                                   // [g][d][key] pad 33
    float* Vs = Kt + KT_FLOATS;                       // [key][512]
    float* qs = Vs + VS_FLOATS;                       // [sub][g][512]
    float* ws = qs + QS_FLOATS;                       // [sub][g][r][32]

    const int bn   = blockIdx.x;                      // b*NCH + n
    const int b    = bn >> 3;
    const int sp   = blockIdx.y;
    const int tid  = threadIdx.x;
    const int wid  = tid >> 5;
    const int lane = tid & 31;
    const int sub  = wid >> 2;
    const int g    = wid & 3;

    // Stage K (transposed) and V
    const float* kch = k + (size_t)bn * KLAT * 512;
    const float* vch = v + (size_t)bn * KLAT * 512;
    for (int idx = tid; idx < KLAT * 512; idx += 256) {
        int key = idx >> 9, col = idx & 511;
        Kt[((col >> 7) * 128 + (col & 127)) * 33 + key] = kch[idx];
        Vs[idx] = vch[idx];
    }
    __syncthreads();

    const int   cnt_bn = cnt[bn];
    const int*  lst    = list + bn * T_;
    const float scale  = 0.08838834764831845f;        // 1/sqrt(128)

    float* qs_w = qs + (sub * 4 + g) * (NREP * D_);
    float* ws_w = ws + (sub * 4 + g) * (NREP * KLAT);
    const float* ktg = Kt + g * 128 * 33;
    const float* vsg = Vs + g * D_;

    // Precompute fragment coords that depend only on lane (d0 = lane*4)
    const int d0  = lane * 4;
    const int km  = d0 & 15;                          // (lane&3)*4
    const int khi = km >> 3;
    const int tigA = (km & 7) >> 1;                   // 0 or 2
    const int sA   = (d0 >> 4) & 3;
    const int dhi  = d0 >> 6;                         // 0 or 1 within r-block? (d0<128 -> 0/1)

    for (int base = 2 * sp; base < cnt_bn; base += 2 * SPLITS) {
        const int ti = base + sub;
        if (ti >= cnt_bn) continue;
        const int t  = lst[ti];
        const int bt = b * T_ + t;

        // stage this token's q for group g (512 floats, 4 float4/lane)
        const float4* qsrc = (const float4*)(q + (size_t)bt * C_ + g * (NREP * D_));
        float4* qdst = (float4*)qs_w;
        #pragma unroll
        for (int i = 0; i < 4; i++) qdst[i * 32 + lane] = qsrc[i * 32 + lane];
        __syncwarp();

        // phase 1: lane = key; scores for 4 rep heads
        float s[NREP] = {0.f, 0.f, 0.f, 0.f};
        #pragma unroll 8
        for (int d4 = 0; d4 < D_; d4 += 4) {
            float kt0 = ktg[(d4 + 0) * 33 + lane];
            float kt1 = ktg[(d4 + 1) * 33 + lane];
            float kt2 = ktg[(d4 + 2) * 33 + lane];
            float kt3 = ktg[(d4 + 3) * 33 + lane];
            #pragma unroll
            for (int r = 0; r < NREP; r++) {
                const float4 qv = *(const float4*)(qs_w + r * D_ + d4);
                s[r] = fmaf(kt0, qv.x, s[r]);
                s[r] = fmaf(kt1, qv.y, s[r]);
                s[r] = fmaf(kt2, qv.z, s[r]);
                s[r] = fmaf(kt3, qv.w, s[r]);
            }
        }

        // phase 2: softmax over 32 keys
        #pragma unroll
        for (int r = 0; r < NREP; r++) {
            float sc = s[r] * scale;
            float m = sc;
            #pragma unroll
            for (int o = 16; o > 0; o >>= 1)
                m = fmaxf(m, __shfl_xor_sync(0xFFFFFFFFu, m, o));
            float e = expf(sc - m);
            float sum = e;
            #pragma unroll
            for (int o = 16; o > 0; o >>= 1)
                sum += __shfl_xor_sync(0xFFFFFFFFu, sum, o);
            ws_w[r * KLAT + lane] = e / sum;
        }
        __syncwarp();

        // phase 3: lane = d-chunk; accumulate over keys from smem V
        float4 acc[NREP];
        #pragma unroll
        for (int r = 0; r < NREP; r++) acc[r] = make_float4(0.f, 0.f, 0.f, 0.f);
        #pragma unroll 8
        for (int key = 0; key < KLAT; key++) {
            float4 vv = *(const float4*)(vsg + key * 512 + lane * 4);
            #pragma unroll
            for (int r = 0; r < NREP; r++) {
                float w = ws_w[r * KLAT + key];
                acc[r].x = fmaf(w, vv.x, acc[r].x);
                acc[r].y = fmaf(w, vv.y, acc[r].y);
                acc[r].z = fmaf(w, vv.z, acc[r].z);
                acc[r].w = fmaf(w, vv.w, acc[r].w);
            }
        }

        // write yA in fragment-A fp16 order (nchC = C/64 = 32 chunks/rowblk)
        const int rbA    = bt >> 7;
        const int tA     = (bt >> 4) & 7;
        const int g8A    = bt & 7;
        const int rowbit = (bt >> 3) & 1;
        const int slot   = (khi << 1) | rowbit;
        uint32_t* ybase = (uint32_t*)(yA + (size_t)rbA * 32 * 8192);
        #pragma unroll
        for (int r = 0; r < NREP; r++) {
            const int kglob = g * 512 + r * 128 + d0;
            const int c     = kglob >> 6;
            const int ul    = (tA * 4 + sA) * 32 + g8A * 4 + tigA;
            uint32_t* p = ybase + (size_t)c * 4096 + ul * 4 + slot;
            p[0] = pack_h2(acc[r].x, acc[r].y);
            p[4] = pack_h2(acc[r].z, acc[r].w);   // next unit, same slot
        }
    }
}

// ---------------------------------------------------------------------------
// Launch. Inputs: x, channel_states, channel_mask, Wq, Wk, Wv, Wo, gate.
// ---------------------------------------------------------------------------
extern "C" void kernel_launch(void* const* d_in, const int* in_sizes, int n_in,
                              void* d_out, int out_size)
{
    const float* x    = (const float*)d_in[0];
    const float* cs   = (const float*)d_in[1];
    const int*   mask = (const int*)d_in[2];
    const float* Wq   = (const float*)d_in[3];
    const float* Wk   = (const float*)d_in[4];
    const float* Wv   = (const float*)d_in[5];
    const float* Wo   = (const float*)d_in[6];
    const float* gate = (const float*)d_in[7];
    float* out = (float*)d_out;

    float *q, *kk, *vv, *part;
    int *list, *cnt;
    __half *xA, *csA, *yA, *WqB, *WkB, *WvB, *WoB;
    cudaGetSymbolAddress((void**)&q,    g_q);
    cudaGetSymbolAddress((void**)&kk,   g_k);
    cudaGetSymbolAddress((void**)&vv,   g_v);
    cudaGetSymbolAddress((void**)&part, g_part);
    cudaGetSymbolAddress((void**)&list, g_list);
    cudaGetSymbolAddress((void**)&cnt,  g_cnt);
    cudaGetSymbolAddress((void**)&xA,   g_xA);
    cudaGetSymbolAddress((void**)&csA,  g_csA);
    cudaGetSymbolAddress((void**)&yA,   g_yA);
    cudaGetSymbolAddress((void**)&WqB,  g_WqB);
    cudaGetSymbolAddress((void**)&WkB,  g_WkB);
    cudaGetSymbolAddress((void**)&WvB,  g_WvB);
    cudaGetSymbolAddress((void**)&WoB,  g_WoB);

    cudaFuncSetAttribute(mma_gemm_kernel,
                         cudaFuncAttributeMaxDynamicSharedMemorySize, GEMM_SMEM);
    cudaFuncSetAttribute(attn2_kernel,
                         cudaFuncAttributeMaxDynamicSharedMemorySize, ATTN_SMEM);

    const int M1  = B_ * T_;          // 2048
    const int Mkv = B_ * NCH * KLAT;  // 512
    const int Nkv = NKV * D_;         // 512

    // idx 0-2: Q operands + lists. idx 3 = Q GEMM (ncu capture slot).
    reformat_A_tiled<<<dim3(C_ / 64, M1 / 128), 256>>>(x, xA, C_);       // 0
    reformat_B_tiled<<<dim3(C_ / 128, C_ / 64), 256>>>(Wq, WqB, C_, C_); // 1
    build_lists_kernel<<<B_, T_>>>(mask, list, cnt);                     // 2
    mma_gemm_kernel<<<dim3(C_ / BN, M1 / BM, 1), 256, GEMM_SMEM>>>(      // 3
        xA, WqB, q, M1, C_, C_, C_, nullptr);

    // K/V path
    reformat_A_tiled<<<dim3(C_ / 64, Mkv / 128), 256>>>(cs, csA, C_);
    reformat_B_tiled<<<dim3(Nkv / 128, C_ / 64), 256>>>(Wk, WkB, C_, Nkv);
    reformat_B_tiled<<<dim3(Nkv / 128, C_ / 64), 256>>>(Wv, WvB, C_, Nkv);
    mma_gemm_kernel<<<dim3(Nkv / BN, Mkv / BM, KV_SPLIT), 256, GEMM_SMEM>>>(
        csA, WkB, part, Mkv, Nkv, C_, C_ / KV_SPLIT, nullptr);
    reduce_split_kernel<<<(Mkv * Nkv) / 1024, 256>>>(part, kk, Mkv * Nkv);
    mma_gemm_kernel<<<dim3(Nkv / BN, Mkv / BM, KV_SPLIT), 256, GEMM_SMEM>>>(
        csA, WvB, part, Mkv, Nkv, C_, C_ / KV_SPLIT, nullptr);
    reduce_split_kernel<<<(Mkv * Nkv) / 1024, 256>>>(part, vv, Mkv * Nkv);

    // Attention -> writes yA directly in fragment order
    attn2_kernel<<<dim3(B_ * NCH, SPLITS), 256, ATTN_SMEM>>>(
        q, kk, vv, yA, list, cnt);

    // Output projection + tanh(gate)
    reformat_B_tiled<<<dim3(C_ / 128, C_ / 64), 256>>>(Wo, WoB, C_, C_);
    mma_gemm_kernel<<<dim3(C_ / BN, M1 / BM, 1), 256, GEMM_SMEM>>>(
        yA, WoB, out, M1, C_, C_, C_, gate);
}

// round 15
// speedup vs baseline: 8.0055x; 1.0457x over previous
#include <cuda_runtime.h>
#include <cuda_fp16.h>
#include <math.h>
#include <cstdint>

// ---------------------------------------------------------------------------
// Problem constants
// ---------------------------------------------------------------------------
#define B_   2
#define T_   1024
#define C_   2048
#define NCH  8
#define KLAT 32
#define NKV  4
#define NREP 4
#define D_   128

#define KV_SPLIT 8
#define SPLITS  9          // attn token-list splits: 16*9 = 144 blocks ~ 1 wave

// Scratch (device globals; allocation is forbidden)
__device__ float  g_q[B_ * T_ * C_];                 // 16 MB
__device__ float  g_k[B_ * NCH * KLAT * NKV * D_];   // 1 MB
__device__ float  g_v[B_ * NCH * KLAT * NKV * D_];   // 1 MB
__device__ float  g_part[KV_SPLIT * 512 * 512];      // 8 MB split-K partials
__device__ int    g_list[B_ * NCH * T_];             // token lists per channel
__device__ int    g_cnt[B_ * NCH];
// Fragment-order fp16 operands
__device__ __half g_xA [B_ * T_ * C_];               // 8 MB
__device__ __half g_csA[B_ * NCH * KLAT * C_];       // 2 MB
__device__ __half g_yA [B_ * T_ * C_];               // 8 MB (written by attn2)
__device__ __half g_WqB[C_ * C_];                    // 8 MB
__device__ __half g_WkB[C_ * NKV * D_];              // 2 MB
__device__ __half g_WvB[C_ * NKV * D_];              // 2 MB
__device__ __half g_WoB[C_ * C_];                    // 8 MB

// ---------------------------------------------------------------------------
// Helpers
// ---------------------------------------------------------------------------
__device__ __forceinline__ uint32_t smem_u32(const void* p) {
    uint32_t a;
    asm("{ .reg .u64 t; cvta.to.shared.u64 t, %1; cvt.u32.u64 %0, t; }"
        : "=r"(a) : "l"(p));
    return a;
}

__device__ __forceinline__ uint32_t pack_h2(float a, float b) {
    __half2 h = __halves2half2(__float2half_rn(a), __float2half_rn(b));
    return *(uint32_t*)&h;
}

// ---------------------------------------------------------------------------
// Tiled reformat A: fp32 [M,K] row-major -> fp16 fragment order (m16n8k16).
// One block = one (128-row, 64-k) chunk. Coalesced float4 reads, smem
// scatter, contiguous 16 KB chunk write.
// ---------------------------------------------------------------------------
__global__ void __launch_bounds__(256) reformat_A_tiled(
    const float* __restrict__ src, __half* __restrict__ dst, int K)
{
    __shared__ uint32_t su[4096];      // 16 KB = one A chunk
    const int tid = threadIdx.x;
    const int cB  = blockIdx.x;        // k-chunk (K/64)
    const int rb  = blockIdx.y;        // 128-row block
    const int nch = K >> 6;

    const float* s0 = src + (size_t)rb * 128 * K + cB * 64;
    #pragma unroll
    for (int j = 0; j < 8; j++) {
        int idx = tid + j * 256;                 // 2048 float4
        int row = idx >> 4, c4 = idx & 15;
        float4 v = *(const float4*)(s0 + (size_t)row * K + c4 * 4);
        int t = row >> 4, g8 = row & 7, rowbit = (row >> 3) & 1;
        int k4 = c4 * 4;                         // 0,4,...,60
        int s  = k4 >> 4;
        int km = k4 & 15;                        // 0,4,8,12
        int khi = km >> 3;
        int tig = (km & 7) >> 1;                 // 0 or 2
        int uu  = (t * 4 + s) * 32 + g8 * 4 + tig;
        int slot = (khi << 1) | rowbit;
        su[uu * 4 + slot]       = pack_h2(v.x, v.y);
        su[(uu + 1) * 4 + slot] = pack_h2(v.z, v.w);
    }
    __syncthreads();
    uint4* dout = (uint4*)(dst + ((size_t)rb * nch + cB) * 8192);
    const uint4* sin = (const uint4*)su;
    #pragma unroll
    for (int j = 0; j < 4; j++)
        dout[tid + j * 256] = sin[tid + j * 256];
}

// ---------------------------------------------------------------------------
// Tiled reformat B: fp32 [K,N] row-major -> fp16 fragment order.
// One block = (64-k chunk) x (128-n slice). Each 128-n slice chunk is a
// contiguous 16 KB block at ((nb256*nch + c)*16384 + half*8192) halfs.
// ---------------------------------------------------------------------------
__global__ void __launch_bounds__(256) reformat_B_tiled(
    const float* __restrict__ src, __half* __restrict__ dst, int K, int N)
{
    __shared__ __half sh[64][136];     // 64 k x 128 n (+8 pad)
    const int tid = threadIdx.x;
    const int nslice = blockIdx.x;     // 128-n slice
    const int cB = blockIdx.y;         // k-chunk
    const int nch = K >> 6;
    const int nb = nslice >> 1, half = nslice & 1;
    const int n0 = nslice * 128;

    const float* s0 = src + (size_t)cB * 64 * N + n0;
    #pragma unroll
    for (int j = 0; j < 8; j++) {
        int idx = tid + j * 256;                 // 2048 float4
        int kr = idx >> 5, c4 = idx & 31;
        float4 v = *(const float4*)(s0 + (size_t)kr * N + c4 * 4);
        __half2 h01 = __halves2half2(__float2half_rn(v.x), __float2half_rn(v.y));
        __half2 h23 = __halves2half2(__float2half_rn(v.z), __float2half_rn(v.w));
        *(__half2*)&sh[kr][c4 * 4]     = h01;
        *(__half2*)&sh[kr][c4 * 4 + 2] = h23;
    }
    __syncthreads();

    uint2* dout = (uint2*)(dst + (((size_t)nb * nch + cB) * 4096 +
                                  (size_t)half * 2048) * 4);
    #pragma unroll
    for (int j = 0; j < 8; j++) {
        int o = tid + j * 256;                   // 2048 uint2
        int lane2 = o & 31, grp = o >> 5;        // grp 0..63 (local)
        int s  = grp & 3;
        int ntl = grp >> 2;                      // 0..15 local nt
        int g8 = lane2 >> 2, tig = lane2 & 3;
        int nl = ntl * 8 + g8;                   // 0..127 within slice
        int kp = s * 16 + 2 * tig;
        uint32_t lo = (uint32_t)__half_as_ushort(sh[kp][nl]) |
                      ((uint32_t)__half_as_ushort(sh[kp + 1][nl]) << 16);
        uint32_t hi = (uint32_t)__half_as_ushort(sh[kp + 8][nl]) |
                      ((uint32_t)__half_as_ushort(sh[kp + 9][nl]) << 16);
        dout[o] = make_uint2(lo, hi);
    }
}

// ---------------------------------------------------------------------------
// fp16 mma.sync GEMM (fp32 accumulate), fragment-order operands.
// Block tile 128x128, 8 warps (2m x 4n), warp tile 64x32, K-chunk 64.
// 3-stage cp.async pipeline, 96 KB smem -> 2 CTAs/SM (16 warps).
// ---------------------------------------------------------------------------
#define BM 128
#define BN 128
#define STAGES 3
#define A_BYTES (BM * 64 * 2)                  // 16384 per chunk
#define B_BYTES (BN * 64 * 2)                  // 16384 per chunk
#define STAGE_BYTES (A_BYTES + B_BYTES)        // 32768
#define GEMM_SMEM (STAGES * STAGE_BYTES)       // 98304

__global__ void __launch_bounds__(256, 2) mma_gemm_kernel(
    const __half* __restrict__ Afrag, const __half* __restrict__ Bfrag,
    float* __restrict__ Cout, int M, int N, int K, int k_len,
    const float* __restrict__ scale_ptr)
{
    extern __shared__ char smem[];
    const uint32_t s_base = smem_u32(smem);

    const int tid    = threadIdx.x;
    const int lane   = tid & 31;
    const int wid    = tid >> 5;
    const int warp_m = wid & 1;   // 2 warps in m (64 rows each)
    const int warp_n = wid >> 1;  // 4 warps in n (32 cols each)

    const int rb  = blockIdx.y;
    const int nb  = blockIdx.x;                  // 128-col tile
    const int z   = blockIdx.z;
    const int nchK = K >> 6;
    const int kc0 = z * (k_len >> 6);
    const int nch = k_len >> 6;
    float* outp = Cout + (size_t)z * M * N;

    const __half* AC = Afrag + (size_t)rb * nchK * 8192;
    // B chunk for 128-col tile nb: contiguous 8192 halfs inside the
    // (nb256, chunk) 16384-half block, at half-slice (nb&1).
    const __half* BC = Bfrag + (size_t)(nb >> 1) * nchK * 16384
                             + (size_t)(nb & 1) * 8192;

    auto issue = [&](int chunk, int buf) {
        uint32_t sb = s_base + buf * STAGE_BYTES;
        const __half* ga = AC + (size_t)(kc0 + chunk) * 8192;
        const __half* gb = BC + (size_t)(kc0 + chunk) * 16384;
        #pragma unroll
        for (int j = 0; j < 4; j++)
            asm volatile("cp.async.cg.shared.global [%0], [%1], 16;"
                :: "r"(sb + (tid + j * 256) * 16), "l"(ga + (tid + j * 256) * 8));
        #pragma unroll
        for (int j = 0; j < 4; j++)
            asm volatile("cp.async.cg.shared.global [%0], [%1], 16;"
                :: "r"(sb + A_BYTES + (tid + j * 256) * 16),
                   "l"(gb + (tid + j * 256) * 8));
        asm volatile("cp.async.commit_group;" ::: "memory");
    };

    float acc[4][4][4];
    #pragma unroll
    for (int a = 0; a < 4; a++)
        #pragma unroll
        for (int b = 0; b < 4; b++)
            #pragma unroll
            for (int c = 0; c < 4; c++) acc[a][b][c] = 0.0f;

    const int npro = (STAGES - 1 < nch) ? (STAGES - 1) : nch;
    for (int p = 0; p < npro; p++) issue(p, p % STAGES);

    for (int i = 0; i < nch; i++) {
        asm volatile("cp.async.wait_group %0;" :: "n"(STAGES - 2) : "memory");
        __syncthreads();

        const uint32_t ab = s_base + (i % STAGES) * STAGE_BYTES;
        const uint32_t bb = ab + A_BYTES;

        #pragma unroll
        for (int s = 0; s < 4; s++) {
            uint32_t areg[4][4];
            #pragma unroll
            for (int mt = 0; mt < 4; mt++) {
                int t = warp_m * 4 + mt;
                uint32_t addr = ab + ((t * 4 + s) * 32 + lane) * 16;
                asm volatile("ld.shared.v4.b32 {%0,%1,%2,%3}, [%4];"
                    : "=r"(areg[mt][0]), "=r"(areg[mt][1]),
                      "=r"(areg[mt][2]), "=r"(areg[mt][3])
                    : "r"(addr));
            }
            uint32_t breg[4][2];
            #pragma unroll
            for (int nt8 = 0; nt8 < 4; nt8++) {
                int nt = warp_n * 4 + nt8;       // 0..15 local nt
                uint32_t addr = bb + ((nt * 4 + s) * 32 + lane) * 8;
                asm volatile("ld.shared.v2.b32 {%0,%1}, [%2];"
                    : "=r"(breg[nt8][0]), "=r"(breg[nt8][1])
                    : "r"(addr));
            }
            #pragma unroll
            for (int mt = 0; mt < 4; mt++)
                #pragma unroll
                for (int nt8 = 0; nt8 < 4; nt8++)
                    asm volatile(
                        "mma.sync.aligned.m16n8k16.row.col.f32.f16.f16.f32 "
                        "{%0,%1,%2,%3}, {%4,%5,%6,%7}, {%8,%9}, {%0,%1,%2,%3};"
                        : "+f"(acc[mt][nt8][0]), "+f"(acc[mt][nt8][1]),
                          "+f"(acc[mt][nt8][2]), "+f"(acc[mt][nt8][3])
                        : "r"(areg[mt][0]), "r"(areg[mt][1]),
                          "r"(areg[mt][2]), "r"(areg[mt][3]),
                          "r"(breg[nt8][0]), "r"(breg[nt8][1]));
        }

        if (i + STAGES - 1 < nch)
            issue(i + STAGES - 1, (i + STAGES - 1) % STAGES);
    }

    // Epilogue
    float scale = 1.0f;
    if (scale_ptr) scale = tanhf(*scale_ptr);
    const int m0 = rb * BM, n0 = nb * BN;
    const int g = lane >> 2, tig = lane & 3;
    #pragma unroll
    for (int mt = 0; mt < 4; mt++) {
        int row = m0 + warp_m * 64 + mt * 16 + g;
        #pragma unroll
        for (int nt8 = 0; nt8 < 4; nt8++) {
            int col = n0 + warp_n * 32 + nt8 * 8 + 2 * tig;
            float2 v0, v1;
            v0.x = acc[mt][nt8][0] * scale; v0.y = acc[mt][nt8][1] * scale;
            v1.x = acc[mt][nt8][2] * scale; v1.y = acc[mt][nt8][3] * scale;
            *(float2*)(outp + (size_t)row * N + col) = v0;
            *(float2*)(outp + (size_t)(row + 8) * N + col) = v1;
        }
    }
}

// ---------------------------------------------------------------------------
// Deterministic split-K reduction: out[i] = sum_z part[z][i]
// ---------------------------------------------------------------------------
__global__ void __launch_bounds__(256) reduce_split_kernel(
    const float* __restrict__ part, float* __restrict__ out, int n)
{
    int i = (blockIdx.x * 256 + threadIdx.x) * 4;
    if (i < n) {
        float4 s = *(const float4*)(part + i);
        #pragma unroll
        for (int zz = 1; zz < KV_SPLIT; zz++) {
            float4 p = *(const float4*)(part + (size_t)zz * n + i);
            s.x += p.x; s.y += p.y; s.z += p.z; s.w += p.w;
        }
        *(float4*)(out + i) = s;
    }
}

// ---------------------------------------------------------------------------
// Build per-(batch,channel) token lists. Grid = B_, block = T_ threads.
// ---------------------------------------------------------------------------
__global__ void __launch_bounds__(T_) build_lists_kernel(
    const int* __restrict__ mask, int* __restrict__ list, int* __restrict__ cnt)
{
    __shared__ int scnt[NCH];
    const int b = blockIdx.x;
    if (threadIdx.x < NCH) scnt[threadIdx.x] = 0;
    __syncthreads();
    const int t = threadIdx.x;
    const int n = mask[b * T_ + t];
    const int pos = atomicAdd(&scnt[n], 1);
    list[(b * NCH + n) * T_ + pos] = t;
    __syncthreads();
    if (threadIdx.x < NCH) cnt[b * NCH + threadIdx.x] = scnt[threadIdx.x];
}

// ---------------------------------------------------------------------------
// Channel-grouped attention; writes yA DIRECTLY in fragment-A fp16 order.
// Block = (channel bn, split sp), 256 threads = 2 tokens x 4 kv-groups.
// ---------------------------------------------------------------------------
#define KT_FLOATS (4 * 128 * 33)                       // 16896
#define VS_FLOATS (KLAT * 512)                         // 16384
#define QS_FLOATS (2 * 4 * NREP * D_)                  // 4096
#define WS_FLOATS (2 * 4 * NREP * KLAT)                // 512
#define ATTN_SMEM ((KT_FLOATS + VS_FLOATS + QS_FLOATS + WS_FLOATS) * 4)

__global__ void __launch_bounds__(256, 1) attn2_kernel(
    const float* __restrict__ q, const float* __restrict__ k,
    const float* __restrict__ v, __half* __restrict__ yA,
    const int* __restrict__ list, const int* __restrict__ cnt)
{
    extern __shared__ float sm[];
    float* Kt = sm;                                   // [g][d][key] pad 33
    float* Vs = Kt + KT_FLOATS;                       // [key][512]
    float* qs = Vs + VS_FLOATS;                       // [sub][g][512]
    float* ws = qs + QS_FLOATS;                       // [sub][g][r][32]

    const int bn   = blockIdx.x;                      // b*NCH + n
    const int b    = bn >> 3;
    const int sp   = blockIdx.y;
    const int tid  = threadIdx.x;
    const int wid  = tid >> 5;
    const int lane = tid & 31;
    const int sub  = wid >> 2;
    const int g    = wid & 3;

    // Stage K (transposed) and V
    const float* kch = k + (size_t)bn * KLAT * 512;
    const float* vch = v + (size_t)bn * KLAT * 512;
    for (int idx = tid; idx < KLAT * 512; idx += 256) {
        int key = idx >> 9, col = idx & 511;
        Kt[((col >> 7) * 128 + (col & 127)) * 33 + key] = kch[idx];
        Vs[idx] = vch[idx];
    }
    __syncthreads();

    const int   cnt_bn = cnt[bn];
    const int*  lst    = list + bn * T_;
    const float scale  = 0.08838834764831845f;        // 1/sqrt(128)

    float* qs_w = qs + (sub * 4 + g) * (NREP * D_);
    float* ws_w = ws + (sub * 4 + g) * (NREP * KLAT);
    const float* ktg = Kt + g * 128 * 33;
    const float* vsg = Vs + g * D_;

    // Fragment coords that depend only on lane (d0 = lane*4)
    const int d0  = lane * 4;
    const int km  = d0 & 15;
    const int khi = km >> 3;
    const int tigA = (km & 7) >> 1;                   // 0 or 2
    const int sA   = (d0 >> 4) & 3;

    for (int base = 2 * sp; base < cnt_bn; base += 2 * SPLITS) {
        const int ti = base + sub;
        if (ti >= cnt_bn) continue;
        const int t  = lst[ti];
        const int bt = b * T_ + t;

        // stage this token's q for group g (512 floats, 4 float4/lane)
        const float4* qsrc = (const float4*)(q + (size_t)bt * C_ + g * (NREP * D_));
        float4* qdst = (float4*)qs_w;
        #pragma unroll
        for (int i = 0; i < 4; i++) qdst[i * 32 + lane] = qsrc[i * 32 + lane];
        __syncwarp();

        // phase 1: lane = key; scores for 4 rep heads
        float s[NREP] = {0.f, 0.f, 0.f, 0.f};
        #pragma unroll 8
        for (int d4 = 0; d4 < D_; d4 += 4) {
            float kt0 = ktg[(d4 + 0) * 33 + lane];
            float kt1 = ktg[(d4 + 1) * 33 + lane];
            float kt2 = ktg[(d4 + 2) * 33 + lane];
            float kt3 = ktg[(d4 + 3) * 33 + lane];
            #pragma unroll
            for (int r = 0; r < NREP; r++) {
                const float4 qv = *(const float4*)(qs_w + r * D_ + d4);
                s[r] = fmaf(kt0, qv.x, s[r]);
                s[r] = fmaf(kt1, qv.y, s[r]);
                s[r] = fmaf(kt2, qv.z, s[r]);
                s[r] = fmaf(kt3, qv.w, s[r]);
            }
        }

        // phase 2: softmax over 32 keys
        #pragma unroll
        for (int r = 0; r < NREP; r++) {
            float sc = s[r] * scale;
            float m = sc;
            #pragma unroll
            for (int o = 16; o > 0; o >>= 1)
                m = fmaxf(m, __shfl_xor_sync(0xFFFFFFFFu, m, o));
            float e = expf(sc - m);
            float sum = e;
            #pragma unroll
            for (int o = 16; o > 0; o >>= 1)
                sum += __shfl_xor_sync(0xFFFFFFFFu, sum, o);
            ws_w[r * KLAT + lane] = e / sum;
        }
        __syncwarp();

        // phase 3: lane = d-chunk; accumulate over keys from smem V
        float4 acc[NREP];
        #pragma unroll
        for (int r = 0; r < NREP; r++) acc[r] = make_float4(0.f, 0.f, 0.f, 0.f);
        #pragma unroll 8
        for (int key = 0; key < KLAT; key++) {
            float4 vv = *(const float4*)(vsg + key * 512 + lane * 4);
            #pragma unroll
            for (int r = 0; r < NREP; r++) {
                float w = ws_w[r * KLAT + key];
                acc[r].x = fmaf(w, vv.x, acc[r].x);
                acc[r].y = fmaf(w, vv.y, acc[r].y);
                acc[r].z = fmaf(w, vv.z, acc[r].z);
                acc[r].w = fmaf(w, vv.w, acc[r].w);
            }
        }

        // write yA in fragment-A fp16 order
        const int rbA    = bt >> 7;
        const int tA     = (bt >> 4) & 7;
        const int g8A    = bt & 7;
        const int rowbit = (bt >> 3) & 1;
        const int slot   = (khi << 1) | rowbit;
        uint32_t* ybase = (uint32_t*)(yA + (size_t)rbA * 32 * 8192);
        #pragma unroll
        for (int r = 0; r < NREP; r++) {
            const int kglob = g * 512 + r * 128 + d0;
            const int c     = kglob >> 6;
            const int ul    = (tA * 4 + sA) * 32 + g8A * 4 + tigA;
            uint32_t* p = ybase + (size_t)c * 4096 + ul * 4 + slot;
            p[0] = pack_h2(acc[r].x, acc[r].y);
            p[4] = pack_h2(acc[r].z, acc[r].w);   // next unit, same slot
        }
    }
}

// ---------------------------------------------------------------------------
// Launch. Inputs: x, channel_states, channel_mask, Wq, Wk, Wv, Wo, gate.
// ---------------------------------------------------------------------------
extern "C" void kernel_launch(void* const* d_in, const int* in_sizes, int n_in,
                              void* d_out, int out_size)
{
    const float* x    = (const float*)d_in[0];
    const float* cs   = (const float*)d_in[1];
    const int*   mask = (const int*)d_in[2];
    const float* Wq   = (const float*)d_in[3];
    const float* Wk   = (const float*)d_in[4];
    const float* Wv   = (const float*)d_in[5];
    const float* Wo   = (const float*)d_in[6];
    const float* gate = (const float*)d_in[7];
    float* out = (float*)d_out;

    float *q, *kk, *vv, *part;
    int *list, *cnt;
    __half *xA, *csA, *yA, *WqB, *WkB, *WvB, *WoB;
    cudaGetSymbolAddress((void**)&q,    g_q);
    cudaGetSymbolAddress((void**)&kk,   g_k);
    cudaGetSymbolAddress((void**)&vv,   g_v);
    cudaGetSymbolAddress((void**)&part, g_part);
    cudaGetSymbolAddress((void**)&list, g_list);
    cudaGetSymbolAddress((void**)&cnt,  g_cnt);
    cudaGetSymbolAddress((void**)&xA,   g_xA);
    cudaGetSymbolAddress((void**)&csA,  g_csA);
    cudaGetSymbolAddress((void**)&yA,   g_yA);
    cudaGetSymbolAddress((void**)&WqB,  g_WqB);
    cudaGetSymbolAddress((void**)&WkB,  g_WkB);
    cudaGetSymbolAddress((void**)&WvB,  g_WvB);
    cudaGetSymbolAddress((void**)&WoB,  g_WoB);

    cudaFuncSetAttribute(mma_gemm_kernel,
                         cudaFuncAttributeMaxDynamicSharedMemorySize, GEMM_SMEM);
    cudaFuncSetAttribute(attn2_kernel,
                         cudaFuncAttributeMaxDynamicSharedMemorySize, ATTN_SMEM);

    const int M1  = B_ * T_;          // 2048
    const int Mkv = B_ * NCH * KLAT;  // 512
    const int Nkv = NKV * D_;         // 512

    // idx 0-2: Q operands + lists. idx 3 = Q GEMM (ncu capture slot).
    reformat_A_tiled<<<dim3(C_ / 64, M1 / 128), 256>>>(x, xA, C_);       // 0
    reformat_B_tiled<<<dim3(C_ / 128, C_ / 64), 256>>>(Wq, WqB, C_, C_); // 1
    build_lists_kernel<<<B_, T_>>>(mask, list, cnt);                     // 2
    mma_gemm_kernel<<<dim3(C_ / BN, M1 / BM, 1), 256, GEMM_SMEM>>>(      // 3
        xA, WqB, q, M1, C_, C_, C_, nullptr);

    // K/V path
    reformat_A_tiled<<<dim3(C_ / 64, Mkv / 128), 256>>>(cs, csA, C_);
    reformat_B_tiled<<<dim3(Nkv / 128, C_ / 64), 256>>>(Wk, WkB, C_, Nkv);
    reformat_B_tiled<<<dim3(Nkv / 128, C_ / 64), 256>>>(Wv, WvB, C_, Nkv);
    mma_gemm_kernel<<<dim3(Nkv / BN, Mkv / BM, KV_SPLIT), 256, GEMM_SMEM>>>(
        csA, WkB, part, Mkv, Nkv, C_, C_ / KV_SPLIT, nullptr);
    reduce_split_kernel<<<(Mkv * Nkv) / 1024, 256>>>(part, kk, Mkv * Nkv);
    mma_gemm_kernel<<<dim3(Nkv / BN, Mkv / BM, KV_SPLIT), 256, GEMM_SMEM>>>(
        csA, WvB, part, Mkv, Nkv, C_, C_ / KV_SPLIT, nullptr);
    reduce_split_kernel<<<(Mkv * Nkv) / 1024, 256>>>(part, vv, Mkv * Nkv);

    // Attention -> writes yA directly in fragment order
    attn2_kernel<<<dim3(B_ * NCH, SPLITS), 256, ATTN_SMEM>>>(
        q, kk, vv, yA, list, cnt);

    // Output projection + tanh(gate)
    reformat_B_tiled<<<dim3(C_ / 128, C_ / 64), 256>>>(Wo, WoB, C_, C_);
    mma_gemm_kernel<<<dim3(C_ / BN, M1 / BM, 1), 256, GEMM_SMEM>>>(
        yA, WoB, out, M1, C_, C_, C_, gate);
}